// round 1
// baseline (speedup 1.0000x reference)
#include <cuda_runtime.h>
#include <math.h>

#define NN 50000
#define NE 640000

// ---------------- scratch (static device globals; no allocation) ----------------
__device__ float g_agg[NN * 128];
__device__ float g_h0[NN * 128];
__device__ float g_h1[NN * 128];
__device__ float g_h2[NN * 64];
__device__ float g_deg[NN];
__device__ float g_invdeg[NN];
__device__ int   g_is64;

// ---------------- edge-index dtype detection ----------------
// int64 little-endian values < 50000 => every odd 32-bit word is 0.
__global__ void detect_kernel(const int* __restrict__ w) {
    __shared__ int flag;
    if (threadIdx.x == 0) flag = 0;
    __syncthreads();
    if (w[threadIdx.x * 2 + 1] != 0) atomicExch(&flag, 1);
    __syncthreads();
    if (threadIdx.x == 0) g_is64 = (flag == 0) ? 1 : 0;
}

__device__ __forceinline__ int2 load_edge(const void* __restrict__ ei, int e) {
    int2 r;
    if (g_is64) {
        const long long* p = (const long long*)ei;
        r.x = (int)p[e];
        r.y = (int)p[NE + e];
    } else {
        const int* p = (const int*)ei;
        r.x = p[e];
        r.y = p[NE + e];
    }
    return r;
}

// ---------------- zero / degree ----------------
__global__ void zero_kernel(float* __restrict__ p, int n) {
    int i = blockIdx.x * blockDim.x + threadIdx.x;
    int stride = gridDim.x * blockDim.x;
    for (; i < n; i += stride) p[i] = 0.0f;
}

__global__ void count_deg(const void* __restrict__ ei) {
    int e = blockIdx.x * blockDim.x + threadIdx.x;
    if (e >= NE) return;
    int2 sd = load_edge(ei, e);
    atomicAdd(&g_deg[sd.y], 1.0f);
}

__global__ void invdeg_kernel() {
    int i = blockIdx.x * blockDim.x + threadIdx.x;
    if (i < NN) g_invdeg[i] = 1.0f / fmaxf(g_deg[i], 1.0f);
}

// ---------------- edge gather/scatter (sum aggregation via vector RED) ----------------
__device__ __forceinline__ void red_add_v4(float* a, float4 v) {
    asm volatile("red.global.add.v4.f32 [%0], {%1,%2,%3,%4};"
                 :: "l"(a), "f"(v.x), "f"(v.y), "f"(v.z), "f"(v.w)
                 : "memory");
}

// C = 128: one warp per edge, lane -> float4 chunk
__global__ void scatter128(const float* __restrict__ feat, const void* __restrict__ ei) {
    int gid  = blockIdx.x * blockDim.x + threadIdx.x;
    int e    = gid >> 5;
    int lane = gid & 31;
    if (e >= NE) return;
    int2 sd = load_edge(ei, e);
    float4 v = ((const float4*)(feat + (size_t)sd.x * 128))[lane];
    red_add_v4(g_agg + (size_t)sd.y * 128 + lane * 4, v);
}

// C = 64: 16 lanes per edge (2 edges per warp)
__global__ void scatter64(const float* __restrict__ feat, const void* __restrict__ ei) {
    int gid = blockIdx.x * blockDim.x + threadIdx.x;
    int e   = gid >> 4;
    int li  = gid & 15;
    if (e >= NE) return;
    int2 sd = load_edge(ei, e);
    float4 v = ((const float4*)(feat + (size_t)sd.x * 64))[li];
    red_add_v4(g_agg + (size_t)sd.y * 64 + li * 4, v);
}

// ---------------- dual-source GEMM: out = (A1 * invdeg) @ W1 + A2 @ W2 + bias ----------------
// A1: [M,K1] (aggregate, row-scaled by g_invdeg), A2: [M,K2], W: [K,BN] row-major, out: [M,BN]
template <int BN, int TN, int K1, int K2, bool RELU>
__global__ __launch_bounds__(256) void gemm_dual(
    const float* __restrict__ A1, const float* __restrict__ A2,
    const float* __restrict__ W1, const float* __restrict__ W2,
    const float* __restrict__ bias, float* __restrict__ out) {
    constexpr int BM = 128, BK = 16, TM = 8;
    constexpr int AST = BM + 4;  // pad: 16B-aligned rows, reduced STS conflicts

    __shared__ __align__(16) float As[BK][AST];
    __shared__ __align__(16) float Bs[BK][BN];

    const int tid  = threadIdx.x;
    const int tcol = tid % (BN / TN);   // 0..15
    const int trow = tid / (BN / TN);   // 0..15
    const int m0   = blockIdx.x * BM;

    float acc[TM][TN];
#pragma unroll
    for (int i = 0; i < TM; i++)
#pragma unroll
        for (int j = 0; j < TN; j++) acc[i][j] = 0.0f;

    auto load_tile = [&](const float* __restrict__ A, int KA, int koff,
                         const float* __restrict__ W, bool scale) {
        // A tile: BM x BK, stored transposed As[k][m]
#pragma unroll
        for (int l = 0; l < (BM * BK / 4) / 256; l++) {
            int idx = tid + l * 256;
            int r   = idx >> 2;
            int kc  = (idx & 3) * 4;
            int grow = m0 + r;
            float4 v = make_float4(0.f, 0.f, 0.f, 0.f);
            if (grow < NN) {
                v = *(const float4*)(A + (size_t)grow * KA + koff + kc);
                if (scale) {
                    float s = g_invdeg[grow];
                    v.x *= s; v.y *= s; v.z *= s; v.w *= s;
                }
            }
            As[kc + 0][r] = v.x;
            As[kc + 1][r] = v.y;
            As[kc + 2][r] = v.z;
            As[kc + 3][r] = v.w;
        }
        // B tile: BK x BN
#pragma unroll
        for (int l = 0; l < (BN * BK / 4) / 256; l++) {
            int idx = tid + l * 256;
            int kr  = idx / (BN / 4);
            int cc  = (idx % (BN / 4)) * 4;
            *(float4*)&Bs[kr][cc] = *(const float4*)(W + (size_t)(koff + kr) * BN + cc);
        }
    };

    auto compute = [&]() {
#pragma unroll
        for (int k = 0; k < BK; k++) {
            float a[TM], b[TN];
#pragma unroll
            for (int i = 0; i < TM; i += 4)
                *(float4*)&a[i] = *(const float4*)&As[k][trow * TM + i];
#pragma unroll
            for (int j = 0; j < TN; j += 4)
                *(float4*)&b[j] = *(const float4*)&Bs[k][tcol * TN + j];
#pragma unroll
            for (int i = 0; i < TM; i++)
#pragma unroll
                for (int j = 0; j < TN; j++)
                    acc[i][j] = fmaf(a[i], b[j], acc[i][j]);
        }
    };

    for (int kt = 0; kt < K1; kt += BK) {
        load_tile(A1, K1, kt, W1, true);
        __syncthreads();
        compute();
        __syncthreads();
    }
    for (int kt = 0; kt < K2; kt += BK) {
        load_tile(A2, K2, kt, W2, false);
        __syncthreads();
        compute();
        __syncthreads();
    }

#pragma unroll
    for (int i = 0; i < TM; i++) {
        int grow = m0 + trow * TM + i;
        if (grow >= NN) continue;
#pragma unroll
        for (int j = 0; j < TN; j += 4) {
            float4 o;
            o.x = acc[i][j + 0] + bias[tcol * TN + j + 0];
            o.y = acc[i][j + 1] + bias[tcol * TN + j + 1];
            o.z = acc[i][j + 2] + bias[tcol * TN + j + 2];
            o.w = acc[i][j + 3] + bias[tcol * TN + j + 3];
            if (RELU) {
                o.x = fmaxf(o.x, 0.f); o.y = fmaxf(o.y, 0.f);
                o.z = fmaxf(o.z, 0.f); o.w = fmaxf(o.w, 0.f);
            }
            *(float4*)(out + (size_t)grow * BN + tcol * TN + j) = o;
        }
    }
}

// ---------------- classifier: sigmoid(relu(h2@Wc1+bc1)@Wc2+bc2), warp per row ----------------
__global__ void classifier(const float* __restrict__ h2,
                           const float* __restrict__ Wc1, const float* __restrict__ bc1,
                           const float* __restrict__ Wc2, const float* __restrict__ bc2,
                           float* __restrict__ out) {
    int gid  = blockIdx.x * blockDim.x + threadIdx.x;
    int row  = gid >> 5;
    int lane = gid & 31;
    if (row >= NN) return;

    float r0 = h2[(size_t)row * 64 + lane];
    float r1 = h2[(size_t)row * 64 + 32 + lane];

    float h = bc1[lane];  // lane = hidden unit j (32 hidden units)
#pragma unroll
    for (int k = 0; k < 32; k++)
        h = fmaf(__shfl_sync(0xffffffffu, r0, k), Wc1[k * 32 + lane], h);
#pragma unroll
    for (int k = 0; k < 32; k++)
        h = fmaf(__shfl_sync(0xffffffffu, r1, k), Wc1[(k + 32) * 32 + lane], h);
    h = fmaxf(h, 0.0f);

    float p = h * Wc2[lane];
#pragma unroll
    for (int o = 16; o > 0; o >>= 1) p += __shfl_xor_sync(0xffffffffu, p, o);

    if (lane == 0) out[row] = 1.0f / (1.0f + expf(-(p + bc2[0])));
}

// ---------------- launch ----------------
extern "C" void kernel_launch(void* const* d_in, const int* in_sizes, int n_in,
                              void* d_out, int out_size) {
    const float* x   = (const float*)d_in[0];
    const void*  ei  = d_in[1];
    const float* Wl0 = (const float*)d_in[2];
    const float* Wr0 = (const float*)d_in[3];
    const float* b0  = (const float*)d_in[4];
    const float* Wl1 = (const float*)d_in[5];
    const float* Wr1 = (const float*)d_in[6];
    const float* b1  = (const float*)d_in[7];
    const float* Wl2 = (const float*)d_in[8];
    const float* Wr2 = (const float*)d_in[9];
    const float* b2  = (const float*)d_in[10];
    const float* Wc1 = (const float*)d_in[11];
    const float* bc1 = (const float*)d_in[12];
    const float* Wc2 = (const float*)d_in[13];
    const float* bc2 = (const float*)d_in[14];
    float* out = (float*)d_out;

    float *agg, *h0, *h1, *h2, *deg;
    cudaGetSymbolAddress((void**)&agg, g_agg);
    cudaGetSymbolAddress((void**)&h0, g_h0);
    cudaGetSymbolAddress((void**)&h1, g_h1);
    cudaGetSymbolAddress((void**)&h2, g_h2);
    cudaGetSymbolAddress((void**)&deg, g_deg);

    const int ZB = 256;
    detect_kernel<<<1, 256>>>((const int*)ei);

    // degree (shared by all layers)
    zero_kernel<<<(NN + ZB - 1) / ZB, ZB>>>(deg, NN);
    count_deg<<<(NE + 255) / 256, 256>>>(ei);
    invdeg_kernel<<<(NN + 255) / 256, 256>>>();

    const int GEMM_GRID = (NN + 127) / 128;  // 391

    // layer 0: C_in = 64 -> 128
    zero_kernel<<<2048, ZB>>>(agg, NN * 64);
    scatter64<<<(NE * 16 + 255) / 256, 256>>>(x, ei);
    gemm_dual<128, 8, 64, 64, true><<<GEMM_GRID, 256>>>(agg, x, Wl0, Wr0, b0, h0);

    // layer 1: 128 -> 128
    zero_kernel<<<4096, ZB>>>(agg, NN * 128);
    scatter128<<<(NE * 32 + 255) / 256, 256>>>(h0, ei);
    gemm_dual<128, 8, 128, 128, true><<<GEMM_GRID, 256>>>(agg, h0, Wl1, Wr1, b1, h1);

    // layer 2: 128 -> 64 (no relu)
    zero_kernel<<<4096, ZB>>>(agg, NN * 128);
    scatter128<<<(NE * 32 + 255) / 256, 256>>>(h1, ei);
    gemm_dual<64, 4, 128, 128, false><<<GEMM_GRID, 256>>>(agg, h1, Wl2, Wr2, b2, h2);

    // classifier
    classifier<<<(NN * 32 + 255) / 256, 256>>>(h2, Wc1, bc1, Wc2, bc2, out);
}

// round 2
// speedup vs baseline: 1.4193x; 1.4193x over previous
#include <cuda_runtime.h>
#include <math.h>

#define NN 50000
#define NE 640000

// ---------------- scratch (static device globals; no allocation) ----------------
__device__ float g_agg[NN * 128];
__device__ float g_h0[NN * 128];
__device__ float g_h1[NN * 128];
__device__ float g_h2[NN * 64];
__device__ float g_invdeg[NN];
__device__ int   g_cnt[NN];
__device__ int   g_rowptr[NN];
__device__ int   g_cursor[NN];
__device__ int   g_srcidx[NE];
__device__ int   g_spine[256];
__device__ int   g_is64;

// ---------------- edge-index dtype detection ----------------
// int64 little-endian values < 50000 => every odd 32-bit word is 0.
__global__ void detect_kernel(const int* __restrict__ w) {
    __shared__ int flag;
    if (threadIdx.x == 0) flag = 0;
    __syncthreads();
    if (w[threadIdx.x * 2 + 1] != 0) atomicExch(&flag, 1);
    __syncthreads();
    if (threadIdx.x == 0) g_is64 = (flag == 0) ? 1 : 0;
}

__device__ __forceinline__ int2 load_edge(const void* __restrict__ ei, int e) {
    int2 r;
    if (g_is64) {
        const long long* p = (const long long*)ei;
        r.x = (int)p[e];
        r.y = (int)p[NE + e];
    } else {
        const int* p = (const int*)ei;
        r.x = p[e];
        r.y = p[NE + e];
    }
    return r;
}

// ---------------- CSR build ----------------
__global__ void zero_int(int* __restrict__ p, int n) {
    int i = blockIdx.x * blockDim.x + threadIdx.x;
    int stride = gridDim.x * blockDim.x;
    for (; i < n; i += stride) p[i] = 0;
}

__global__ void count_deg(const void* __restrict__ ei) {
    int e = blockIdx.x * blockDim.x + threadIdx.x;
    if (e >= NE) return;
    int2 sd = load_edge(ei, e);
    atomicAdd(&g_cnt[sd.y], 1);
}

// phase 1: per-block (512) exclusive scan of g_cnt -> g_rowptr (local), totals -> g_spine
__global__ void scan1() {
    __shared__ int wsum[16];
    int i    = blockIdx.x * 512 + threadIdx.x;
    int lane = threadIdx.x & 31;
    int w    = threadIdx.x >> 5;
    int v    = (i < NN) ? g_cnt[i] : 0;
    int s    = v;
#pragma unroll
    for (int o = 1; o < 32; o <<= 1) {
        int t = __shfl_up_sync(0xffffffffu, s, o);
        if (lane >= o) s += t;
    }
    if (lane == 31) wsum[w] = s;
    __syncthreads();
    if (w == 0 && lane < 16) {
        int t = wsum[lane];
#pragma unroll
        for (int o = 1; o < 16; o <<= 1) {
            int u = __shfl_up_sync(0x0000ffffu, t, o);
            if (lane >= o) t += u;
        }
        wsum[lane] = t;
    }
    __syncthreads();
    int base = (w > 0) ? wsum[w - 1] : 0;
    if (i < NN) g_rowptr[i] = base + s - v;
    if (threadIdx.x == 0) g_spine[blockIdx.x] = wsum[15];
}

// phase 2: single-block exclusive scan of spine (nb <= 128)
__global__ void scan2(int nb) {
    __shared__ int wsum[4];
    int tid  = threadIdx.x;
    int lane = tid & 31;
    int w    = tid >> 5;
    int v    = (tid < nb) ? g_spine[tid] : 0;
    int s    = v;
#pragma unroll
    for (int o = 1; o < 32; o <<= 1) {
        int t = __shfl_up_sync(0xffffffffu, s, o);
        if (lane >= o) s += t;
    }
    if (lane == 31) wsum[w] = s;
    __syncthreads();
    if (w == 0 && lane < 4) {
        int t = wsum[lane];
#pragma unroll
        for (int o = 1; o < 4; o <<= 1) {
            int u = __shfl_up_sync(0x0000000fu, t, o);
            if (lane >= o) t += u;
        }
        wsum[lane] = t;
    }
    __syncthreads();
    int base = (w > 0) ? wsum[w - 1] : 0;
    if (tid < nb) g_spine[tid] = base + s - v;
}

// phase 3: finalize rowptr, init cursor, compute invdeg
__global__ void scan3() {
    int i = blockIdx.x * blockDim.x + threadIdx.x;
    if (i >= NN) return;
    int r = g_rowptr[i] + g_spine[i >> 9];
    g_rowptr[i] = r;
    g_cursor[i] = r;
    g_invdeg[i] = 1.0f / fmaxf((float)g_cnt[i], 1.0f);
}

__global__ void fill_csr(const void* __restrict__ ei) {
    int e = blockIdx.x * blockDim.x + threadIdx.x;
    if (e >= NE) return;
    int2 sd = load_edge(ei, e);
    int pos = atomicAdd(&g_cursor[sd.y], 1);
    g_srcidx[pos] = sd.x;
}

// ---------------- CSR mean-aggregation: out[node] = mean(feat[src]) * 1 ----------------
// LPN lanes cooperate per node; each lane owns one float4 chunk (C = LPN*4).
template <int LPN>
__global__ void agg_kernel(const float* __restrict__ feat, float* __restrict__ out) {
    int gid  = blockIdx.x * blockDim.x + threadIdx.x;
    int node = gid / LPN;
    int lane = gid % LPN;
    if (node >= NN) return;
    const int  C     = LPN * 4;
    const int* idx   = g_srcidx + g_rowptr[node];
    int        n     = g_cnt[node];
    float4 acc = make_float4(0.f, 0.f, 0.f, 0.f);
    int j = 0;
    for (; j + 2 <= n; j += 2) {
        int s0 = idx[j];
        int s1 = idx[j + 1];
        float4 v0 = *(const float4*)(feat + (size_t)s0 * C + lane * 4);
        float4 v1 = *(const float4*)(feat + (size_t)s1 * C + lane * 4);
        acc.x += v0.x + v1.x; acc.y += v0.y + v1.y;
        acc.z += v0.z + v1.z; acc.w += v0.w + v1.w;
    }
    if (j < n) {
        float4 v = *(const float4*)(feat + (size_t)idx[j] * C + lane * 4);
        acc.x += v.x; acc.y += v.y; acc.z += v.z; acc.w += v.w;
    }
    float s = g_invdeg[node];
    acc.x *= s; acc.y *= s; acc.z *= s; acc.w *= s;
    *(float4*)(out + (size_t)node * C + lane * 4) = acc;
}

// ---------------- dual-source GEMM, smem double-buffered, 1 sync/tile ----------------
// out = A1 @ W1 + A2 @ W2 + bias   (A1 already scaled by invdeg)
template <int BN, int TN, int K1, int K2, bool RELU>
__global__ __launch_bounds__(256) void gemm_dual(
    const float* __restrict__ A1, const float* __restrict__ A2,
    const float* __restrict__ W1, const float* __restrict__ W2,
    const float* __restrict__ bias, float* __restrict__ out) {
    constexpr int BM = 128, BK = 16, TM = 8;
    constexpr int AST = BM + 4;
    constexpr int NT1 = K1 / BK, NT2 = K2 / BK, NT = NT1 + NT2;
    constexpr int NB4 = (BK * BN) / (4 * 256);  // B float4 loads per thread (2 or 1)

    __shared__ __align__(16) float As[2][BK][AST];
    __shared__ __align__(16) float Bs[2][BK][BN];

    const int tid  = threadIdx.x;
    const int tcol = tid % (BN / TN);
    const int trow = tid / (BN / TN);
    const int m0   = blockIdx.x * BM;

    float acc[TM][TN];
#pragma unroll
    for (int i = 0; i < TM; i++)
#pragma unroll
        for (int j = 0; j < TN; j++) acc[i][j] = 0.0f;

    float4 ra[2];
    float4 rb[NB4];

    auto gload = [&](int t) {
        const float* A; const float* W; int KA, koff;
        if (t < NT1) { A = A1; W = W1; KA = K1; koff = t * BK; }
        else         { A = A2; W = W2; KA = K2; koff = (t - NT1) * BK; }
#pragma unroll
        for (int l = 0; l < 2; l++) {
            int idx  = tid + l * 256;
            int r    = idx >> 2;
            int kc   = (idx & 3) * 4;
            int grow = m0 + r;
            ra[l] = (grow < NN)
                        ? *(const float4*)(A + (size_t)grow * KA + koff + kc)
                        : make_float4(0.f, 0.f, 0.f, 0.f);
        }
#pragma unroll
        for (int l = 0; l < NB4; l++) {
            int idx = tid + l * 256;
            int kr  = idx / (BN / 4);
            int cc  = (idx % (BN / 4)) * 4;
            rb[l] = *(const float4*)(W + (size_t)(koff + kr) * BN + cc);
        }
    };

    auto sstore = [&](int buf) {
#pragma unroll
        for (int l = 0; l < 2; l++) {
            int idx = tid + l * 256;
            int r   = idx >> 2;
            int kc  = (idx & 3) * 4;
            As[buf][kc + 0][r] = ra[l].x;
            As[buf][kc + 1][r] = ra[l].y;
            As[buf][kc + 2][r] = ra[l].z;
            As[buf][kc + 3][r] = ra[l].w;
        }
#pragma unroll
        for (int l = 0; l < NB4; l++) {
            int idx = tid + l * 256;
            int kr  = idx / (BN / 4);
            int cc  = (idx % (BN / 4)) * 4;
            *(float4*)&Bs[buf][kr][cc] = rb[l];
        }
    };

    auto compute = [&](int buf) {
#pragma unroll
        for (int k = 0; k < BK; k++) {
            float a[TM], b[TN];
#pragma unroll
            for (int i = 0; i < TM; i += 4)
                *(float4*)&a[i] = *(const float4*)&As[buf][k][trow * TM + i];
#pragma unroll
            for (int j = 0; j < TN; j += 4)
                *(float4*)&b[j] = *(const float4*)&Bs[buf][k][tcol * TN + j];
#pragma unroll
            for (int i = 0; i < TM; i++)
#pragma unroll
                for (int j = 0; j < TN; j++)
                    acc[i][j] = fmaf(a[i], b[j], acc[i][j]);
        }
    };

    gload(0);
    sstore(0);
    __syncthreads();
#pragma unroll 1
    for (int t = 0; t < NT; t++) {
        if (t + 1 < NT) gload(t + 1);
        compute(t & 1);
        if (t + 1 < NT) sstore((t + 1) & 1);  // other buffer: safe, last read before prev sync
        __syncthreads();
    }

#pragma unroll
    for (int i = 0; i < TM; i++) {
        int grow = m0 + trow * TM + i;
        if (grow >= NN) continue;
#pragma unroll
        for (int j = 0; j < TN; j += 4) {
            float4 o;
            o.x = acc[i][j + 0] + bias[tcol * TN + j + 0];
            o.y = acc[i][j + 1] + bias[tcol * TN + j + 1];
            o.z = acc[i][j + 2] + bias[tcol * TN + j + 2];
            o.w = acc[i][j + 3] + bias[tcol * TN + j + 3];
            if (RELU) {
                o.x = fmaxf(o.x, 0.f); o.y = fmaxf(o.y, 0.f);
                o.z = fmaxf(o.z, 0.f); o.w = fmaxf(o.w, 0.f);
            }
            *(float4*)(out + (size_t)grow * BN + tcol * TN + j) = o;
        }
    }
}

// ---------------- classifier: sigmoid(relu(h2@Wc1+bc1)@Wc2+bc2), warp per row ----------------
__global__ void classifier(const float* __restrict__ h2,
                           const float* __restrict__ Wc1, const float* __restrict__ bc1,
                           const float* __restrict__ Wc2, const float* __restrict__ bc2,
                           float* __restrict__ out) {
    int gid  = blockIdx.x * blockDim.x + threadIdx.x;
    int row  = gid >> 5;
    int lane = gid & 31;
    if (row >= NN) return;

    float r0 = h2[(size_t)row * 64 + lane];
    float r1 = h2[(size_t)row * 64 + 32 + lane];

    float h = bc1[lane];
#pragma unroll
    for (int k = 0; k < 32; k++)
        h = fmaf(__shfl_sync(0xffffffffu, r0, k), Wc1[k * 32 + lane], h);
#pragma unroll
    for (int k = 0; k < 32; k++)
        h = fmaf(__shfl_sync(0xffffffffu, r1, k), Wc1[(k + 32) * 32 + lane], h);
    h = fmaxf(h, 0.0f);

    float p = h * Wc2[lane];
#pragma unroll
    for (int o = 16; o > 0; o >>= 1) p += __shfl_xor_sync(0xffffffffu, p, o);

    if (lane == 0) out[row] = 1.0f / (1.0f + expf(-(p + bc2[0])));
}

// ---------------- launch ----------------
extern "C" void kernel_launch(void* const* d_in, const int* in_sizes, int n_in,
                              void* d_out, int out_size) {
    const float* x   = (const float*)d_in[0];
    const void*  ei  = d_in[1];
    const float* Wl0 = (const float*)d_in[2];
    const float* Wr0 = (const float*)d_in[3];
    const float* b0  = (const float*)d_in[4];
    const float* Wl1 = (const float*)d_in[5];
    const float* Wr1 = (const float*)d_in[6];
    const float* b1  = (const float*)d_in[7];
    const float* Wl2 = (const float*)d_in[8];
    const float* Wr2 = (const float*)d_in[9];
    const float* b2  = (const float*)d_in[10];
    const float* Wc1 = (const float*)d_in[11];
    const float* bc1 = (const float*)d_in[12];
    const float* Wc2 = (const float*)d_in[13];
    const float* bc2 = (const float*)d_in[14];
    float* out = (float*)d_out;

    float *agg, *h0, *h1, *h2;
    int* cnt;
    cudaGetSymbolAddress((void**)&agg, g_agg);
    cudaGetSymbolAddress((void**)&h0, g_h0);
    cudaGetSymbolAddress((void**)&h1, g_h1);
    cudaGetSymbolAddress((void**)&h2, g_h2);
    cudaGetSymbolAddress((void**)&cnt, g_cnt);

    const int NB_SCAN = (NN + 511) / 512;  // 98

    detect_kernel<<<1, 256>>>((const int*)ei);

    // CSR build (shared by all 3 layers)
    zero_int<<<(NN + 255) / 256, 256>>>(cnt, NN);
    count_deg<<<(NE + 255) / 256, 256>>>(ei);
    scan1<<<NB_SCAN, 512>>>();
    scan2<<<1, 128>>>(NB_SCAN);
    scan3<<<(NN + 255) / 256, 256>>>();
    fill_csr<<<(NE + 255) / 256, 256>>>(ei);

    const int GEMM_GRID = (NN + 127) / 128;  // 391

    // layer 0: 64 -> 128
    agg_kernel<16><<<(NN * 16 + 255) / 256, 256>>>(x, agg);
    gemm_dual<128, 8, 64, 64, true><<<GEMM_GRID, 256>>>(agg, x, Wl0, Wr0, b0, h0);

    // layer 1: 128 -> 128
    agg_kernel<32><<<(NN * 32 + 255) / 256, 256>>>(h0, agg);
    gemm_dual<128, 8, 128, 128, true><<<GEMM_GRID, 256>>>(agg, h0, Wl1, Wr1, b1, h1);

    // layer 2: 128 -> 64 (no relu)
    agg_kernel<32><<<(NN * 32 + 255) / 256, 256>>>(h1, agg);
    gemm_dual<64, 4, 128, 128, false><<<GEMM_GRID, 256>>>(agg, h1, Wl2, Wr2, b2, h2);

    // classifier
    classifier<<<(NN * 32 + 255) / 256, 256>>>(h2, Wc1, bc1, Wc2, bc2, out);
}

// round 4
// speedup vs baseline: 1.9561x; 1.3782x over previous
#include <cuda_runtime.h>
#include <cuda_bf16.h>
#include <math.h>
#include <stdint.h>

#define NN 50000
#define NE 640000

// ---------------- scratch (static device globals; no allocation) ----------------
__device__ float g_agg[NN * 128];
__device__ float g_h0[NN * 128];
__device__ float g_h1[NN * 128];
__device__ float g_h2[NN * 64];
__device__ float g_invdeg[NN];
__device__ int   g_cnt[NN];
__device__ int   g_rowptr[NN];
__device__ int   g_cursor[NN];
__device__ int   g_srcidx[NE];
__device__ int   g_spine[256];
__device__ int   g_is64;
// transposed + hi/lo split weights: slot i holds Wt[N][K] bf16 (k-major rows)
__device__ __nv_bfloat16 g_wt_hi[6][16384];
__device__ __nv_bfloat16 g_wt_lo[6][16384];

// ---------------- helpers ----------------
__device__ __forceinline__ uint32_t smem_u32(const void* p) {
    uint32_t a;
    asm("{ .reg .u64 t; cvta.to.shared.u64 t, %1; cvt.u32.u64 %0, t; }" : "=r"(a) : "l"(p));
    return a;
}
__device__ __forceinline__ void ldsm4(uint32_t& r0, uint32_t& r1, uint32_t& r2, uint32_t& r3,
                                      uint32_t addr) {
    asm volatile("ldmatrix.sync.aligned.m8n8.x4.shared.b16 {%0,%1,%2,%3}, [%4];"
                 : "=r"(r0), "=r"(r1), "=r"(r2), "=r"(r3) : "r"(addr));
}
__device__ __forceinline__ void mma_bf16(float* d, const uint32_t* a, const uint32_t* b) {
    asm volatile(
        "mma.sync.aligned.m16n8k16.row.col.f32.bf16.bf16.f32 "
        "{%0,%1,%2,%3}, {%4,%5,%6,%7}, {%8,%9}, {%0,%1,%2,%3};"
        : "+f"(d[0]), "+f"(d[1]), "+f"(d[2]), "+f"(d[3])
        : "r"(a[0]), "r"(a[1]), "r"(a[2]), "r"(a[3]), "r"(b[0]), "r"(b[1]));
}
__device__ __forceinline__ int sw128(int byte) { return byte ^ ((byte >> 3) & 0x70); }

// ---------------- edge-index dtype detection ----------------
__global__ void detect_kernel(const int* __restrict__ w) {
    __shared__ int flag;
    if (threadIdx.x == 0) flag = 0;
    __syncthreads();
    if (w[threadIdx.x * 2 + 1] != 0) atomicExch(&flag, 1);
    __syncthreads();
    if (threadIdx.x == 0) g_is64 = (flag == 0) ? 1 : 0;
}

__device__ __forceinline__ int2 load_edge(const void* __restrict__ ei, int e) {
    int2 r;
    if (g_is64) {
        const long long* p = (const long long*)ei;
        r.x = (int)p[e];
        r.y = (int)p[NE + e];
    } else {
        const int* p = (const int*)ei;
        r.x = p[e];
        r.y = p[NE + e];
    }
    return r;
}

// ---------------- CSR build ----------------
__global__ void zero_int(int* __restrict__ p, int n) {
    int i = blockIdx.x * blockDim.x + threadIdx.x;
    int stride = gridDim.x * blockDim.x;
    for (; i < n; i += stride) p[i] = 0;
}

__global__ void count_deg(const void* __restrict__ ei) {
    int e = blockIdx.x * blockDim.x + threadIdx.x;
    if (e >= NE) return;
    int2 sd = load_edge(ei, e);
    atomicAdd(&g_cnt[sd.y], 1);
}

__global__ void scan1() {
    __shared__ int wsum[16];
    int i    = blockIdx.x * 512 + threadIdx.x;
    int lane = threadIdx.x & 31;
    int w    = threadIdx.x >> 5;
    int v    = (i < NN) ? g_cnt[i] : 0;
    int s    = v;
#pragma unroll
    for (int o = 1; o < 32; o <<= 1) {
        int t = __shfl_up_sync(0xffffffffu, s, o);
        if (lane >= o) s += t;
    }
    if (lane == 31) wsum[w] = s;
    __syncthreads();
    if (w == 0 && lane < 16) {
        int t = wsum[lane];
#pragma unroll
        for (int o = 1; o < 16; o <<= 1) {
            int u = __shfl_up_sync(0x0000ffffu, t, o);
            if (lane >= o) t += u;
        }
        wsum[lane] = t;
    }
    __syncthreads();
    int base = (w > 0) ? wsum[w - 1] : 0;
    if (i < NN) g_rowptr[i] = base + s - v;
    if (threadIdx.x == 0) g_spine[blockIdx.x] = wsum[15];
}

__global__ void scan2(int nb) {
    __shared__ int wsum[4];
    int tid  = threadIdx.x;
    int lane = tid & 31;
    int w    = tid >> 5;
    int v    = (tid < nb) ? g_spine[tid] : 0;
    int s    = v;
#pragma unroll
    for (int o = 1; o < 32; o <<= 1) {
        int t = __shfl_up_sync(0xffffffffu, s, o);
        if (lane >= o) s += t;
    }
    if (lane == 31) wsum[w] = s;
    __syncthreads();
    if (w == 0 && lane < 4) {
        int t = wsum[lane];
#pragma unroll
        for (int o = 1; o < 4; o <<= 1) {
            int u = __shfl_up_sync(0x0000000fu, t, o);
            if (lane >= o) t += u;
        }
        wsum[lane] = t;
    }
    __syncthreads();
    int base = (w > 0) ? wsum[w - 1] : 0;
    if (tid < nb) g_spine[tid] = base + s - v;
}

__global__ void scan3() {
    int i = blockIdx.x * blockDim.x + threadIdx.x;
    if (i >= NN) return;
    int r = g_rowptr[i] + g_spine[i >> 9];
    g_rowptr[i] = r;
    g_cursor[i] = r;
    g_invdeg[i] = 1.0f / fmaxf((float)g_cnt[i], 1.0f);
}

__global__ void fill_csr(const void* __restrict__ ei) {
    int e = blockIdx.x * blockDim.x + threadIdx.x;
    if (e >= NE) return;
    int2 sd = load_edge(ei, e);
    int pos = atomicAdd(&g_cursor[sd.y], 1);
    g_srcidx[pos] = sd.x;
}

// ---------------- CSR mean-aggregation ----------------
template <int LPN>
__global__ void agg_kernel(const float* __restrict__ feat, float* __restrict__ out) {
    int gid  = blockIdx.x * blockDim.x + threadIdx.x;
    int node = gid / LPN;
    int lane = gid % LPN;
    if (node >= NN) return;
    const int  C   = LPN * 4;
    const int* idx = g_srcidx + g_rowptr[node];
    int        n   = g_cnt[node];
    float4 acc = make_float4(0.f, 0.f, 0.f, 0.f);
    int j = 0;
    for (; j + 2 <= n; j += 2) {
        int s0 = idx[j];
        int s1 = idx[j + 1];
        float4 v0 = *(const float4*)(feat + (size_t)s0 * C + lane * 4);
        float4 v1 = *(const float4*)(feat + (size_t)s1 * C + lane * 4);
        acc.x += v0.x + v1.x; acc.y += v0.y + v1.y;
        acc.z += v0.z + v1.z; acc.w += v0.w + v1.w;
    }
    if (j < n) {
        float4 v = *(const float4*)(feat + (size_t)idx[j] * C + lane * 4);
        acc.x += v.x; acc.y += v.y; acc.z += v.z; acc.w += v.w;
    }
    float s = g_invdeg[node];
    acc.x *= s; acc.y *= s; acc.z *= s; acc.w *= s;
    *(float4*)(out + (size_t)node * C + lane * 4) = acc;
}

// ---------------- weight transpose + hi/lo split: Wt[n*K+k] = split(W[k*N+n]) ----------------
__global__ void wsplit(const float* W0, const float* W1, const float* W2,
                       const float* W3, const float* W4, const float* W5) {
    int b = blockIdx.x;
    const float* W;
    int K, N;
    switch (b) {
        case 0: W = W0; K = 64;  N = 128; break;
        case 1: W = W1; K = 64;  N = 128; break;
        case 2: W = W2; K = 128; N = 128; break;
        case 3: W = W3; K = 128; N = 128; break;
        case 4: W = W4; K = 128; N = 64;  break;
        default: W = W5; K = 128; N = 64; break;
    }
    __nv_bfloat16* dh = g_wt_hi[b];
    __nv_bfloat16* dl = g_wt_lo[b];
    for (int i = threadIdx.x; i < K * N; i += blockDim.x) {
        int n = i / K, k = i % K;
        float v = W[k * N + n];
        __nv_bfloat16 h = __float2bfloat16_rn(v);
        __nv_bfloat16 l = __float2bfloat16_rn(v - __bfloat162float(h));
        dh[i] = h;
        dl[i] = l;
    }
}

// ---------------- warp-MMA dual-source GEMM, bf16x3 (hi/lo split) ----------------
// out[M,NOUT] = A1 @ WtL^T + A2 @ WtR^T + bias   (Wt stored [NOUT][KSRC] k-major)
template <int KSRC, int NOUT, bool RELU>
__global__ __launch_bounds__(256, 2) void gemm_mma(
    const float* __restrict__ A1, const float* __restrict__ A2,
    const __nv_bfloat16* __restrict__ BLh, const __nv_bfloat16* __restrict__ BLl,
    const __nv_bfloat16* __restrict__ BRh, const __nv_bfloat16* __restrict__ BRl,
    const float* __restrict__ bias, float* __restrict__ out) {
    extern __shared__ char smem[];
    // A hi [128][64]bf16 swizzled (16KB), A lo (16KB), B hi [NOUT][64] , B lo
    constexpr int ALO = 16384, BHO = 32768, BLO = 32768 + NOUT * 128;

    uint32_t sb = smem_u32(smem);
    const int tid = threadIdx.x, wid = tid >> 5, lid = tid & 31;
    const int wm = wid & 3, wn = wid >> 2;
    const int m0 = blockIdx.x * 128;

    constexpr int WN     = NOUT / 2;   // 64 or 32 cols per warp
    constexpr int NTILES = WN / 8;     // 8 or 4
    constexpr int NPAIR  = NTILES / 2; // 4 or 2
    constexpr int KH     = KSRC / 64;
    constexpr int NPH    = 2 * KH;

    float acc[2][NTILES][4];
#pragma unroll
    for (int i = 0; i < 2; i++)
#pragma unroll
        for (int j = 0; j < NTILES; j++)
#pragma unroll
            for (int c = 0; c < 4; c++) acc[i][j][c] = 0.0f;

    for (int p = 0; p < NPH; p++) {
        const float* A = (p < KH) ? A1 : A2;
        const __nv_bfloat16* Bh = (p < KH) ? BLh : BRh;
        const __nv_bfloat16* Bl = (p < KH) ? BLl : BRl;
        int kofs = (p % KH) * 64;

        // ---- stage A tile [128][64] fp32 -> bf16 hi/lo, swizzled ----
#pragma unroll
        for (int i = 0; i < 8; i++) {
            int idx = tid + i * 256;     // 0..2047
            int r   = idx >> 4;          // row 0..127
            int c4  = idx & 15;          // float4 col
            int grow = m0 + r;
            float4 v = make_float4(0.f, 0.f, 0.f, 0.f);
            if (grow < NN) v = *(const float4*)(A + (size_t)grow * KSRC + kofs + c4 * 4);
            __nv_bfloat16 hx = __float2bfloat16_rn(v.x);
            __nv_bfloat16 hy = __float2bfloat16_rn(v.y);
            __nv_bfloat16 hz = __float2bfloat16_rn(v.z);
            __nv_bfloat16 hw = __float2bfloat16_rn(v.w);
            __nv_bfloat16 lx = __float2bfloat16_rn(v.x - __bfloat162float(hx));
            __nv_bfloat16 ly = __float2bfloat16_rn(v.y - __bfloat162float(hy));
            __nv_bfloat16 lz = __float2bfloat16_rn(v.z - __bfloat162float(hz));
            __nv_bfloat16 lw = __float2bfloat16_rn(v.w - __bfloat162float(hw));
            uint32_t h01 = ((uint32_t)__bfloat16_as_ushort(hy) << 16) | __bfloat16_as_ushort(hx);
            uint32_t h23 = ((uint32_t)__bfloat16_as_ushort(hw) << 16) | __bfloat16_as_ushort(hz);
            uint32_t l01 = ((uint32_t)__bfloat16_as_ushort(ly) << 16) | __bfloat16_as_ushort(lx);
            uint32_t l23 = ((uint32_t)__bfloat16_as_ushort(lw) << 16) | __bfloat16_as_ushort(lz);
            int sw = sw128(r * 128 + c4 * 8);
            *(uint2*)(smem + sw)       = make_uint2(h01, h23);
            *(uint2*)(smem + ALO + sw) = make_uint2(l01, l23);
        }
        // ---- stage B tile [NOUT][64] bf16 hi/lo, swizzled ----
#pragma unroll
        for (int i = 0; i < NOUT / 32; i++) {
            int idx = tid + i * 256;
            int r   = idx >> 3;          // row 0..NOUT-1
            int c8  = idx & 7;           // 16B chunk
            uint4 hv = *(const uint4*)(Bh + (size_t)r * KSRC + kofs + c8 * 8);
            uint4 lv = *(const uint4*)(Bl + (size_t)r * KSRC + kofs + c8 * 8);
            int sw = sw128(r * 128 + c8 * 16);
            *(uint4*)(smem + BHO + sw) = hv;
            *(uint4*)(smem + BLO + sw) = lv;
        }
        __syncthreads();

        // ---- compute: 4 k-steps of 16 ----
#pragma unroll
        for (int ks = 0; ks < 4; ks++) {
            int k0b = ks * 32;  // bytes
            uint32_t ah[2][4], al[2][4];
#pragma unroll
            for (int mt = 0; mt < 2; mt++) {
                int mrow = wm * 32 + mt * 16 + (lid & 15);
                int byte = mrow * 128 + k0b + (lid >> 4) * 16;
                int sw   = sw128(byte);
                ldsm4(ah[mt][0], ah[mt][1], ah[mt][2], ah[mt][3], sb + sw);
                ldsm4(al[mt][0], al[mt][1], al[mt][2], al[mt][3], sb + ALO + sw);
            }
#pragma unroll
            for (int ntp = 0; ntp < NPAIR; ntp++) {
                int nrow = wn * WN + ntp * 16 + ((lid >> 4) & 1) * 8 + (lid & 7);
                int byte = nrow * 128 + k0b + ((lid >> 3) & 1) * 16;
                int sw   = sw128(byte);
                uint32_t bh[4], bl[4];
                ldsm4(bh[0], bh[1], bh[2], bh[3], sb + BHO + sw);
                ldsm4(bl[0], bl[1], bl[2], bl[3], sb + BLO + sw);
#pragma unroll
                for (int mt = 0; mt < 2; mt++) {
#pragma unroll
                    for (int j = 0; j < 2; j++) {
                        int nt = ntp * 2 + j;
                        mma_bf16(acc[mt][nt], ah[mt], bh + 2 * j);
                        mma_bf16(acc[mt][nt], al[mt], bh + 2 * j);
                        mma_bf16(acc[mt][nt], ah[mt], bl + 2 * j);
                    }
                }
            }
        }
        __syncthreads();
    }

    // ---- epilogue ----
    const int r  = lid >> 2;
    const int c2 = (lid & 3) * 2;
#pragma unroll
    for (int mt = 0; mt < 2; mt++) {
        int row0 = m0 + wm * 32 + mt * 16 + r;
        int row1 = row0 + 8;
#pragma unroll
        for (int nt = 0; nt < NTILES; nt++) {
            int col = wn * WN + nt * 8 + c2;
            float bx = __ldg(bias + col), by = __ldg(bias + col + 1);
            float2 o0 = make_float2(acc[mt][nt][0] + bx, acc[mt][nt][1] + by);
            float2 o1 = make_float2(acc[mt][nt][2] + bx, acc[mt][nt][3] + by);
            if (RELU) {
                o0.x = fmaxf(o0.x, 0.f); o0.y = fmaxf(o0.y, 0.f);
                o1.x = fmaxf(o1.x, 0.f); o1.y = fmaxf(o1.y, 0.f);
            }
            if (row0 < NN) *(float2*)(out + (size_t)row0 * NOUT + col) = o0;
            if (row1 < NN) *(float2*)(out + (size_t)row1 * NOUT + col) = o1;
        }
    }
}

// ---------------- classifier ----------------
__global__ void classifier(const float* __restrict__ h2,
                           const float* __restrict__ Wc1, const float* __restrict__ bc1,
                           const float* __restrict__ Wc2, const float* __restrict__ bc2,
                           float* __restrict__ out) {
    int gid  = blockIdx.x * blockDim.x + threadIdx.x;
    int row  = gid >> 5;
    int lane = gid & 31;
    if (row >= NN) return;

    float r0 = h2[(size_t)row * 64 + lane];
    float r1 = h2[(size_t)row * 64 + 32 + lane];

    float h = bc1[lane];
#pragma unroll
    for (int k = 0; k < 32; k++)
        h = fmaf(__shfl_sync(0xffffffffu, r0, k), Wc1[k * 32 + lane], h);
#pragma unroll
    for (int k = 0; k < 32; k++)
        h = fmaf(__shfl_sync(0xffffffffu, r1, k), Wc1[(k + 32) * 32 + lane], h);
    h = fmaxf(h, 0.0f);

    float p = h * Wc2[lane];
#pragma unroll
    for (int o = 16; o > 0; o >>= 1) p += __shfl_xor_sync(0xffffffffu, p, o);

    if (lane == 0) out[row] = 1.0f / (1.0f + expf(-(p + bc2[0])));
}

// ---------------- launch ----------------
extern "C" void kernel_launch(void* const* d_in, const int* in_sizes, int n_in,
                              void* d_out, int out_size) {
    const float* x   = (const float*)d_in[0];
    const void*  ei  = d_in[1];
    const float* Wl0 = (const float*)d_in[2];
    const float* Wr0 = (const float*)d_in[3];
    const float* b0  = (const float*)d_in[4];
    const float* Wl1 = (const float*)d_in[5];
    const float* Wr1 = (const float*)d_in[6];
    const float* b1  = (const float*)d_in[7];
    const float* Wl2 = (const float*)d_in[8];
    const float* Wr2 = (const float*)d_in[9];
    const float* b2  = (const float*)d_in[10];
    const float* Wc1 = (const float*)d_in[11];
    const float* bc1 = (const float*)d_in[12];
    const float* Wc2 = (const float*)d_in[13];
    const float* bc2 = (const float*)d_in[14];
    float* out = (float*)d_out;

    float *agg, *h0, *h1, *h2;
    int* cnt;
    __nv_bfloat16 *wth, *wtl;
    cudaGetSymbolAddress((void**)&agg, g_agg);
    cudaGetSymbolAddress((void**)&h0, g_h0);
    cudaGetSymbolAddress((void**)&h1, g_h1);
    cudaGetSymbolAddress((void**)&h2, g_h2);
    cudaGetSymbolAddress((void**)&cnt, g_cnt);
    cudaGetSymbolAddress((void**)&wth, g_wt_hi);
    cudaGetSymbolAddress((void**)&wtl, g_wt_lo);

    const int SMEM_128 = 32768 + 2 * 128 * 128;  // 65536
    const int SMEM_64  = 32768 + 2 * 64 * 128;   // 49152
    cudaFuncSetAttribute(gemm_mma<64, 128, true>,  cudaFuncAttributeMaxDynamicSharedMemorySize, SMEM_128);
    cudaFuncSetAttribute(gemm_mma<128, 128, true>, cudaFuncAttributeMaxDynamicSharedMemorySize, SMEM_128);
    cudaFuncSetAttribute(gemm_mma<128, 64, false>, cudaFuncAttributeMaxDynamicSharedMemorySize, SMEM_64);

    const int NB_SCAN = (NN + 511) / 512;  // 98

    detect_kernel<<<1, 256>>>((const int*)ei);

    // CSR build (shared by all 3 layers)
    zero_int<<<(NN + 255) / 256, 256>>>(cnt, NN);
    count_deg<<<(NE + 255) / 256, 256>>>(ei);
    scan1<<<NB_SCAN, 512>>>();
    scan2<<<1, 128>>>(NB_SCAN);
    scan3<<<(NN + 255) / 256, 256>>>();
    fill_csr<<<(NE + 255) / 256, 256>>>(ei);

    // transposed + split weights
    wsplit<<<6, 256>>>(Wl0, Wr0, Wl1, Wr1, Wl2, Wr2);

    const int GEMM_GRID = (NN + 127) / 128;  // 391

    // layer 0: 64 -> 128
    agg_kernel<16><<<(NN * 16 + 255) / 256, 256>>>(x, agg);
    gemm_mma<64, 128, true><<<GEMM_GRID, 256, SMEM_128>>>(
        agg, x, wth + 0 * 16384, wtl + 0 * 16384, wth + 1 * 16384, wtl + 1 * 16384, b0, h0);

    // layer 1: 128 -> 128
    agg_kernel<32><<<(NN * 32 + 255) / 256, 256>>>(h0, agg);
    gemm_mma<128, 128, true><<<GEMM_GRID, 256, SMEM_128>>>(
        agg, h0, wth + 2 * 16384, wtl + 2 * 16384, wth + 3 * 16384, wtl + 3 * 16384, b1, h1);

    // layer 2: 128 -> 64 (no relu)
    agg_kernel<32><<<(NN * 32 + 255) / 256, 256>>>(h1, agg);
    gemm_mma<128, 64, false><<<GEMM_GRID, 256, SMEM_64>>>(
        agg, h1, wth + 4 * 16384, wtl + 4 * 16384, wth + 5 * 16384, wtl + 5 * 16384, b2, h2);

    // classifier
    classifier<<<(NN * 32 + 255) / 256, 256>>>(h2, Wc1, bc1, Wc2, bc2, out);
}

// round 6
// speedup vs baseline: 2.1124x; 1.0799x over previous
#include <cuda_runtime.h>
#include <cuda_bf16.h>
#include <math.h>
#include <stdint.h>

#define NN 50000
#define NE 640000

// ---------------- scratch (static device globals; no allocation) ----------------
__device__ float g_agg[NN * 128];
__device__ float g_h0[NN * 128];
__device__ float g_h1[NN * 128];
__device__ float g_invdeg[NN];
__device__ int   g_cnt[NN];
__device__ int   g_rowptr[NN];
__device__ int   g_cursor[NN];
__device__ int   g_srcidx[NE];
__device__ int   g_spine[128];
__device__ int   g_is64;
// transposed + hi/lo split weights: slots 0-3 = Wl0,Wr0,Wl1,Wr1 ([N][K] k-major);
// slot 4 = concat [Wl2 rows 0-63 | Wr2 rows 64-127], K=128
__device__ __nv_bfloat16 g_wt_hi[5][16384];
__device__ __nv_bfloat16 g_wt_lo[5][16384];

// ---------------- helpers ----------------
__device__ __forceinline__ uint32_t smem_u32(const void* p) {
    uint32_t a;
    asm("{ .reg .u64 t; cvta.to.shared.u64 t, %1; cvt.u32.u64 %0, t; }" : "=r"(a) : "l"(p));
    return a;
}
__device__ __forceinline__ void ldsm4(uint32_t& r0, uint32_t& r1, uint32_t& r2, uint32_t& r3,
                                      uint32_t addr) {
    asm volatile("ldmatrix.sync.aligned.m8n8.x4.shared.b16 {%0,%1,%2,%3}, [%4];"
                 : "=r"(r0), "=r"(r1), "=r"(r2), "=r"(r3) : "r"(addr));
}
__device__ __forceinline__ void mma_bf16(float* d, const uint32_t* a, const uint32_t* b) {
    asm volatile(
        "mma.sync.aligned.m16n8k16.row.col.f32.bf16.bf16.f32 "
        "{%0,%1,%2,%3}, {%4,%5,%6,%7}, {%8,%9}, {%0,%1,%2,%3};"
        : "+f"(d[0]), "+f"(d[1]), "+f"(d[2]), "+f"(d[3])
        : "r"(a[0]), "r"(a[1]), "r"(a[2]), "r"(a[3]), "r"(b[0]), "r"(b[1]));
}
__device__ __forceinline__ int sw128(int byte) { return byte ^ ((byte >> 3) & 0x70); }

// ---------------- detect edge dtype + zero degree counters (merged) ----------------
__global__ void detect_zero(const int* __restrict__ w) {
    int i = blockIdx.x * blockDim.x + threadIdx.x;
    if (i < NN) g_cnt[i] = 0;
    if (blockIdx.x == 0) {
        __shared__ int flag;
        if (threadIdx.x == 0) flag = 0;
        __syncthreads();
        if (w[threadIdx.x * 2 + 1] != 0) atomicExch(&flag, 1);
        __syncthreads();
        if (threadIdx.x == 0) g_is64 = (flag == 0) ? 1 : 0;
    }
}

__device__ __forceinline__ int2 load_edge(const void* __restrict__ ei, int e) {
    int2 r;
    if (g_is64) {
        const long long* p = (const long long*)ei;
        r.x = (int)p[e];
        r.y = (int)p[NE + e];
    } else {
        const int* p = (const int*)ei;
        r.x = p[e];
        r.y = p[NE + e];
    }
    return r;
}

__global__ void count_deg(const void* __restrict__ ei) {
    int e = blockIdx.x * blockDim.x + threadIdx.x;
    if (e >= NE) return;
    int2 sd = load_edge(ei, e);
    atomicAdd(&g_cnt[sd.y], 1);
}

// phase 1: per-block (512) exclusive scan of g_cnt -> g_rowptr (local), totals -> g_spine
__global__ void scan1() {
    __shared__ int wsum[16];
    int i    = blockIdx.x * 512 + threadIdx.x;
    int lane = threadIdx.x & 31;
    int w    = threadIdx.x >> 5;
    int v    = (i < NN) ? g_cnt[i] : 0;
    int s    = v;
#pragma unroll
    for (int o = 1; o < 32; o <<= 1) {
        int t = __shfl_up_sync(0xffffffffu, s, o);
        if (lane >= o) s += t;
    }
    if (lane == 31) wsum[w] = s;
    __syncthreads();
    if (w == 0 && lane < 16) {
        int t = wsum[lane];
#pragma unroll
        for (int o = 1; o < 16; o <<= 1) {
            int u = __shfl_up_sync(0x0000ffffu, t, o);
            if (lane >= o) t += u;
        }
        wsum[lane] = t;
    }
    __syncthreads();
    int base = (w > 0) ? wsum[w - 1] : 0;
    if (i < NN) g_rowptr[i] = base + s - v;
    if (threadIdx.x == 0) g_spine[blockIdx.x] = wsum[15];
}

// phase 2+3 merged: every block scans the 98-entry spine in smem, applies
__global__ void scan23(int nb) {
    __shared__ int sp[128];
    int t = threadIdx.x;
    if (t < 128) sp[t] = (t < nb) ? g_spine[t] : 0;
    __syncthreads();
#pragma unroll
    for (int o = 1; o < 128; o <<= 1) {
        int v = 0;
        if (t < 128 && t >= o) v = sp[t - o];
        __syncthreads();
        if (t < 128) sp[t] += v;
        __syncthreads();
    }
    int i = blockIdx.x * blockDim.x + t;
    if (i < NN) {
        int blk  = i >> 9;
        int excl = blk ? sp[blk - 1] : 0;
        int r    = g_rowptr[i] + excl;
        g_rowptr[i] = r;
        g_cursor[i] = r;
        g_invdeg[i] = 1.0f / fmaxf((float)g_cnt[i], 1.0f);
    }
}

__global__ void fill_csr(const void* __restrict__ ei) {
    int e = blockIdx.x * blockDim.x + threadIdx.x;
    if (e >= NE) return;
    int2 sd = load_edge(ei, e);
    int pos = atomicAdd(&g_cursor[sd.y], 1);
    g_srcidx[pos] = sd.x;
}

// ---------------- CSR mean-aggregation ----------------
template <int LPN>
__global__ void agg_kernel(const float* __restrict__ feat, float* __restrict__ out) {
    int gid  = blockIdx.x * blockDim.x + threadIdx.x;
    int node = gid / LPN;
    int lane = gid % LPN;
    if (node >= NN) return;
    const int  C   = LPN * 4;
    const int* idx = g_srcidx + g_rowptr[node];
    int        n   = g_cnt[node];
    float4 acc = make_float4(0.f, 0.f, 0.f, 0.f);
    int j = 0;
    for (; j + 2 <= n; j += 2) {
        int s0 = idx[j];
        int s1 = idx[j + 1];
        float4 v0 = *(const float4*)(feat + (size_t)s0 * C + lane * 4);
        float4 v1 = *(const float4*)(feat + (size_t)s1 * C + lane * 4);
        acc.x += v0.x + v1.x; acc.y += v0.y + v1.y;
        acc.z += v0.z + v1.z; acc.w += v0.w + v1.w;
    }
    if (j < n) {
        float4 v = *(const float4*)(feat + (size_t)idx[j] * C + lane * 4);
        acc.x += v.x; acc.y += v.y; acc.z += v.z; acc.w += v.w;
    }
    float s = g_invdeg[node];
    acc.x *= s; acc.y *= s; acc.z *= s; acc.w *= s;
    *(float4*)(out + (size_t)node * C + lane * 4) = acc;
}

// ---------------- weight transpose + hi/lo split ----------------
__global__ void wsplit(const float* W0, const float* W1, const float* W2,
                       const float* W3, const float* W4, const float* W5) {
    int b = blockIdx.x;
    const float* W;
    int K, N, slot, rofs;
    switch (b) {
        case 0: W = W0; K = 64;  N = 128; slot = 0; rofs = 0; break;
        case 1: W = W1; K = 64;  N = 128; slot = 1; rofs = 0; break;
        case 2: W = W2; K = 128; N = 128; slot = 2; rofs = 0; break;
        case 3: W = W3; K = 128; N = 128; slot = 3; rofs = 0; break;
        case 4: W = W4; K = 128; N = 64;  slot = 4; rofs = 0; break;   // Wl2 -> rows 0-63
        default: W = W5; K = 128; N = 64; slot = 4; rofs = 64; break;  // Wr2 -> rows 64-127
    }
    __nv_bfloat16* dh = g_wt_hi[slot] + rofs * 128;
    __nv_bfloat16* dl = g_wt_lo[slot] + rofs * 128;
    for (int i = threadIdx.x; i < K * N; i += blockDim.x) {
        int n = i / K, k = i % K;
        float v = W[k * N + n];
        __nv_bfloat16 h = __float2bfloat16_rn(v);
        __nv_bfloat16 l = __float2bfloat16_rn(v - __bfloat162float(h));
        dh[i] = h;
        dl[i] = l;
    }
}

// ---------------- warp-MMA GEMM, bf16x3 (hi/lo split) ----------------
// DUAL: out = A1 @ WtL^T + A2 @ WtR^T (+bias)(relu)
// !DUAL: out = A1 @ WtL^T
template <int KSRC, int NOUT, bool DUAL, bool RELU, bool BIAS>
__global__ __launch_bounds__(256, 2) void gemm_mma(
    const float* __restrict__ A1, const float* __restrict__ A2,
    const __nv_bfloat16* __restrict__ BLh, const __nv_bfloat16* __restrict__ BLl,
    const __nv_bfloat16* __restrict__ BRh, const __nv_bfloat16* __restrict__ BRl,
    const float* __restrict__ bias, float* __restrict__ out) {
    extern __shared__ char smem[];
    constexpr int ALO = 16384, BHO = 32768, BLO = 32768 + NOUT * 128;

    uint32_t sb = smem_u32(smem);
    const int tid = threadIdx.x, wid = tid >> 5, lid = tid & 31;
    const int wm = wid & 3, wn = wid >> 2;
    const int m0 = blockIdx.x * 128;

    constexpr int WN     = NOUT / 2;
    constexpr int NTILES = WN / 8;
    constexpr int NPAIR  = NTILES / 2;
    constexpr int KH     = KSRC / 64;
    constexpr int NPH    = DUAL ? 2 * KH : KH;

    float acc[2][NTILES][4];
#pragma unroll
    for (int i = 0; i < 2; i++)
#pragma unroll
        for (int j = 0; j < NTILES; j++)
#pragma unroll
            for (int c = 0; c < 4; c++) acc[i][j][c] = 0.0f;

    for (int p = 0; p < NPH; p++) {
        const float* A = (p < KH) ? A1 : A2;
        const __nv_bfloat16* Bh = (p < KH) ? BLh : BRh;
        const __nv_bfloat16* Bl = (p < KH) ? BLl : BRl;
        int kofs = (p % KH) * 64;

        // ---- stage A tile [128][64] fp32 -> bf16 hi/lo, swizzled ----
#pragma unroll
        for (int i = 0; i < 8; i++) {
            int idx = tid + i * 256;
            int r   = idx >> 4;
            int c4  = idx & 15;
            int grow = m0 + r;
            float4 v = make_float4(0.f, 0.f, 0.f, 0.f);
            if (grow < NN) v = *(const float4*)(A + (size_t)grow * KSRC + kofs + c4 * 4);
            __nv_bfloat16 hx = __float2bfloat16_rn(v.x);
            __nv_bfloat16 hy = __float2bfloat16_rn(v.y);
            __nv_bfloat16 hz = __float2bfloat16_rn(v.z);
            __nv_bfloat16 hw = __float2bfloat16_rn(v.w);
            __nv_bfloat16 lx = __float2bfloat16_rn(v.x - __bfloat162float(hx));
            __nv_bfloat16 ly = __float2bfloat16_rn(v.y - __bfloat162float(hy));
            __nv_bfloat16 lz = __float2bfloat16_rn(v.z - __bfloat162float(hz));
            __nv_bfloat16 lw = __float2bfloat16_rn(v.w - __bfloat162float(hw));
            uint32_t h01 = ((uint32_t)__bfloat16_as_ushort(hy) << 16) | __bfloat16_as_ushort(hx);
            uint32_t h23 = ((uint32_t)__bfloat16_as_ushort(hw) << 16) | __bfloat16_as_ushort(hz);
            uint32_t l01 = ((uint32_t)__bfloat16_as_ushort(ly) << 16) | __bfloat16_as_ushort(lx);
            uint32_t l23 = ((uint32_t)__bfloat16_as_ushort(lw) << 16) | __bfloat16_as_ushort(lz);
            int sw = sw128(r * 128 + c4 * 8);
            *(uint2*)(smem + sw)       = make_uint2(h01, h23);
            *(uint2*)(smem + ALO + sw) = make_uint2(l01, l23);
        }
        // ---- stage B tile [NOUT][64] bf16 hi/lo, swizzled ----
#pragma unroll
        for (int i = 0; i < NOUT / 32; i++) {
            int idx = tid + i * 256;
            int r   = idx >> 3;
            int c8  = idx & 7;
            uint4 hv = *(const uint4*)(Bh + (size_t)r * KSRC + kofs + c8 * 8);
            uint4 lv = *(const uint4*)(Bl + (size_t)r * KSRC + kofs + c8 * 8);
            int sw = sw128(r * 128 + c8 * 16);
            *(uint4*)(smem + BHO + sw) = hv;
            *(uint4*)(smem + BLO + sw) = lv;
        }
        __syncthreads();

        // ---- compute: 4 k-steps of 16 ----
#pragma unroll
        for (int ks = 0; ks < 4; ks++) {
            int k0b = ks * 32;
            uint32_t ah[2][4], al[2][4];
#pragma unroll
            for (int mt = 0; mt < 2; mt++) {
                int mrow = wm * 32 + mt * 16 + (lid & 15);
                int byte = mrow * 128 + k0b + (lid >> 4) * 16;
                int sw   = sw128(byte);
                ldsm4(ah[mt][0], ah[mt][1], ah[mt][2], ah[mt][3], sb + sw);
                ldsm4(al[mt][0], al[mt][1], al[mt][2], al[mt][3], sb + ALO + sw);
            }
#pragma unroll
            for (int ntp = 0; ntp < NPAIR; ntp++) {
                int nrow = wn * WN + ntp * 16 + ((lid >> 4) & 1) * 8 + (lid & 7);
                int byte = nrow * 128 + k0b + ((lid >> 3) & 1) * 16;
                int sw   = sw128(byte);
                uint32_t bh[4], bl[4];
                ldsm4(bh[0], bh[1], bh[2], bh[3], sb + BHO + sw);
                ldsm4(bl[0], bl[1], bl[2], bl[3], sb + BLO + sw);
#pragma unroll
                for (int mt = 0; mt < 2; mt++) {
#pragma unroll
                    for (int j = 0; j < 2; j++) {
                        int nt = ntp * 2 + j;
                        mma_bf16(acc[mt][nt], ah[mt], bh + 2 * j);
                        mma_bf16(acc[mt][nt], al[mt], bh + 2 * j);
                        mma_bf16(acc[mt][nt], ah[mt], bl + 2 * j);
                    }
                }
            }
        }
        __syncthreads();
    }

    // ---- epilogue ----
    const int r  = lid >> 2;
    const int c2 = (lid & 3) * 2;
#pragma unroll
    for (int mt = 0; mt < 2; mt++) {
        int row0 = m0 + wm * 32 + mt * 16 + r;
        int row1 = row0 + 8;
#pragma unroll
        for (int nt = 0; nt < NTILES; nt++) {
            int col = wn * WN + nt * 8 + c2;
            float bx = BIAS ? __ldg(bias + col) : 0.f;
            float by = BIAS ? __ldg(bias + col + 1) : 0.f;
            float2 o0 = make_float2(acc[mt][nt][0] + bx, acc[mt][nt][1] + by);
            float2 o1 = make_float2(acc[mt][nt][2] + bx, acc[mt][nt][3] + by);
            if (RELU) {
                o0.x = fmaxf(o0.x, 0.f); o0.y = fmaxf(o0.y, 0.f);
                o1.x = fmaxf(o1.x, 0.f); o1.y = fmaxf(o1.y, 0.f);
            }
            if (row0 < NN) *(float2*)(out + (size_t)row0 * NOUT + col) = o0;
            if (row1 < NN) *(float2*)(out + (size_t)row1 * NOUT + col) = o1;
        }
    }
}

// ---------------- layer-2 finalize + classifier (fused), warp per node ----------------
// ts: [NN][128]; cols 0-63 = t = h1@Wl2 (to aggregate), cols 64-127 = s = h1@Wr2
__global__ void finalize_classifier(const float* __restrict__ ts, const float* __restrict__ b2,
                                    const float* __restrict__ Wc1, const float* __restrict__ bc1,
                                    const float* __restrict__ Wc2, const float* __restrict__ bc2,
                                    float* __restrict__ out) {
    int gid  = blockIdx.x * blockDim.x + threadIdx.x;
    int node = gid >> 5;
    int lane = gid & 31;
    if (node >= NN) return;

    const int* idx = g_srcidx + g_rowptr[node];
    int n = g_cnt[node];
    float2 acc = make_float2(0.f, 0.f);
    int j = 0;
    for (; j + 2 <= n; j += 2) {
        int s0 = idx[j];
        int s1 = idx[j + 1];
        float2 v0 = *(const float2*)(ts + (size_t)s0 * 128 + lane * 2);
        float2 v1 = *(const float2*)(ts + (size_t)s1 * 128 + lane * 2);
        acc.x += v0.x + v1.x;
        acc.y += v0.y + v1.y;
    }
    if (j < n) {
        float2 v = *(const float2*)(ts + (size_t)idx[j] * 128 + lane * 2);
        acc.x += v.x; acc.y += v.y;
    }
    float sc = g_invdeg[node];
    float2 s = *(const float2*)(ts + (size_t)node * 128 + 64 + lane * 2);
    // h2 components at cols 2*lane, 2*lane+1 (no relu on layer 2)
    float vx = acc.x * sc + s.x + __ldg(b2 + lane * 2);
    float vy = acc.y * sc + s.y + __ldg(b2 + lane * 2 + 1);

    // classifier: hidden unit = lane
    float h = __ldg(bc1 + lane);
#pragma unroll
    for (int k = 0; k < 32; k++) {
        float ax = __shfl_sync(0xffffffffu, vx, k);
        float ay = __shfl_sync(0xffffffffu, vy, k);
        h = fmaf(ax, __ldg(Wc1 + (2 * k) * 32 + lane), h);
        h = fmaf(ay, __ldg(Wc1 + (2 * k + 1) * 32 + lane), h);
    }
    h = fmaxf(h, 0.0f);

    float p = h * __ldg(Wc2 + lane);
#pragma unroll
    for (int o = 16; o > 0; o >>= 1) p += __shfl_xor_sync(0xffffffffu, p, o);

    if (lane == 0) out[node] = 1.0f / (1.0f + expf(-(p + bc2[0])));
}

// ---------------- launch ----------------
extern "C" void kernel_launch(void* const* d_in, const int* in_sizes, int n_in,
                              void* d_out, int out_size) {
    const float* x   = (const float*)d_in[0];
    const void*  ei  = d_in[1];
    const float* Wl0 = (const float*)d_in[2];
    const float* Wr0 = (const float*)d_in[3];
    const float* b0  = (const float*)d_in[4];
    const float* Wl1 = (const float*)d_in[5];
    const float* Wr1 = (const float*)d_in[6];
    const float* b1  = (const float*)d_in[7];
    const float* Wl2 = (const float*)d_in[8];
    const float* Wr2 = (const float*)d_in[9];
    const float* b2  = (const float*)d_in[10];
    const float* Wc1 = (const float*)d_in[11];
    const float* bc1 = (const float*)d_in[12];
    const float* Wc2 = (const float*)d_in[13];
    const float* bc2 = (const float*)d_in[14];
    float* out = (float*)d_out;

    float *agg, *h0, *h1;
    __nv_bfloat16 *wth, *wtl;
    cudaGetSymbolAddress((void**)&agg, g_agg);
    cudaGetSymbolAddress((void**)&h0, g_h0);
    cudaGetSymbolAddress((void**)&h1, g_h1);
    cudaGetSymbolAddress((void**)&wth, g_wt_hi);
    cudaGetSymbolAddress((void**)&wtl, g_wt_lo);

    const int SMEM_128 = 32768 + 2 * 128 * 128;  // 65536
    cudaFuncSetAttribute((void*)gemm_mma<64, 128, true, true, true>,
                         cudaFuncAttributeMaxDynamicSharedMemorySize, SMEM_128);
    cudaFuncSetAttribute((void*)gemm_mma<128, 128, true, true, true>,
                         cudaFuncAttributeMaxDynamicSharedMemorySize, SMEM_128);
    cudaFuncSetAttribute((void*)gemm_mma<128, 128, false, false, false>,
                         cudaFuncAttributeMaxDynamicSharedMemorySize, SMEM_128);

    const int NB_SCAN = (NN + 511) / 512;  // 98

    // CSR build (shared by all 3 layers)
    detect_zero<<<(NN + 255) / 256, 256>>>((const int*)ei);
    count_deg<<<(NE + 255) / 256, 256>>>(ei);
    scan1<<<NB_SCAN, 512>>>();
    scan23<<<(NN + 255) / 256, 256>>>(NB_SCAN);
    fill_csr<<<(NE + 255) / 256, 256>>>(ei);

    // transposed + split weights (slot 4 = concat [Wl2; Wr2])
    wsplit<<<6, 256>>>(Wl0, Wr0, Wl1, Wr1, Wl2, Wr2);

    const int GEMM_GRID = (NN + 127) / 128;  // 391

    // layer 0: 64 -> 128  (aggregate-first)
    agg_kernel<16><<<(NN * 16 + 255) / 256, 256>>>(x, agg);
    gemm_mma<64, 128, true, true, true><<<GEMM_GRID, 256, SMEM_128>>>(
        agg, x, wth + 0 * 16384, wtl + 0 * 16384, wth + 1 * 16384, wtl + 1 * 16384, b0, h0);

    // layer 1: 128 -> 128  (aggregate-first)
    agg_kernel<32><<<(NN * 32 + 255) / 256, 256>>>(h0, agg);
    gemm_mma<128, 128, true, true, true><<<GEMM_GRID, 256, SMEM_128>>>(
        agg, h0, wth + 2 * 16384, wtl + 2 * 16384, wth + 3 * 16384, wtl + 3 * 16384, b1, h1);

    // layer 2: transform-first. ts = h1 @ [Wl2 | Wr2]  (cols 0-63 = t, 64-127 = s)
    gemm_mma<128, 128, false, false, false><<<GEMM_GRID, 256, SMEM_128>>>(
        h1, h1, wth + 4 * 16384, wtl + 4 * 16384, wth + 4 * 16384, wtl + 4 * 16384,
        (const float*)0, agg);

    // finalize layer 2 (64-wide gather) + classifier, fused
    finalize_classifier<<<(NN * 32 + 255) / 256, 256>>>(agg, b2, Wc1, bc1, Wc2, bc2, out);
}

// round 7
// speedup vs baseline: 2.1322x; 1.0094x over previous
#include <cuda_runtime.h>
#include <cuda_bf16.h>
#include <math.h>
#include <stdint.h>

#define NN 50000
#define NE 640000

// ---------------- scratch (static device globals; no allocation) ----------------
__device__ float g_agg[NN * 128];
__device__ float g_h0[NN * 128];
__device__ float g_h1[NN * 128];
__device__ float g_invdeg[NN];
__device__ int   g_cnt[NN];
__device__ int   g_rowptr[NN];
__device__ int   g_cursor[NN];
__device__ int   g_srcidx[NE];
__device__ int   g_spine[128];
__device__ int   g_is64;
// transposed + hi/lo split weights: slots 0-3 = Wl0,Wr0,Wl1,Wr1 ([N][K] k-major);
// slot 4 = concat [Wl2 rows 0-63 | Wr2 rows 64-127], K=128
__device__ __nv_bfloat16 g_wt_hi[5][16384];
__device__ __nv_bfloat16 g_wt_lo[5][16384];

// ---------------- helpers ----------------
__device__ __forceinline__ uint32_t smem_u32(const void* p) {
    uint32_t a;
    asm("{ .reg .u64 t; cvta.to.shared.u64 t, %1; cvt.u32.u64 %0, t; }" : "=r"(a) : "l"(p));
    return a;
}
__device__ __forceinline__ void ldsm4(uint32_t& r0, uint32_t& r1, uint32_t& r2, uint32_t& r3,
                                      uint32_t addr) {
    asm volatile("ldmatrix.sync.aligned.m8n8.x4.shared.b16 {%0,%1,%2,%3}, [%4];"
                 : "=r"(r0), "=r"(r1), "=r"(r2), "=r"(r3) : "r"(addr));
}
__device__ __forceinline__ void mma_bf16(float* d, const uint32_t* a, const uint32_t* b) {
    asm volatile(
        "mma.sync.aligned.m16n8k16.row.col.f32.bf16.bf16.f32 "
        "{%0,%1,%2,%3}, {%4,%5,%6,%7}, {%8,%9}, {%0,%1,%2,%3};"
        : "+f"(d[0]), "+f"(d[1]), "+f"(d[2]), "+f"(d[3])
        : "r"(a[0]), "r"(a[1]), "r"(a[2]), "r"(a[3]), "r"(b[0]), "r"(b[1]));
}
__device__ __forceinline__ int sw128(int byte) { return byte ^ ((byte >> 3) & 0x70); }
__device__ __forceinline__ void cpasync16(uint32_t dst, const void* src) {
    asm volatile("cp.async.cg.shared.global [%0], [%1], 16;" :: "r"(dst), "l"(src));
}
#define CP_COMMIT() asm volatile("cp.async.commit_group;" ::: "memory")
#define CP_WAIT0()  asm volatile("cp.async.wait_group 0;" ::: "memory")

// ---------------- detect edge dtype + zero degree counters (merged) ----------------
__global__ void detect_zero(const int* __restrict__ w) {
    int i = blockIdx.x * blockDim.x + threadIdx.x;
    if (i < NN) g_cnt[i] = 0;
    if (blockIdx.x == 0) {
        __shared__ int flag;
        if (threadIdx.x == 0) flag = 0;
        __syncthreads();
        if (w[threadIdx.x * 2 + 1] != 0) atomicExch(&flag, 1);
        __syncthreads();
        if (threadIdx.x == 0) g_is64 = (flag == 0) ? 1 : 0;
    }
}

__device__ __forceinline__ int2 load_edge(const void* __restrict__ ei, int e) {
    int2 r;
    if (g_is64) {
        const long long* p = (const long long*)ei;
        r.x = (int)p[e];
        r.y = (int)p[NE + e];
    } else {
        const int* p = (const int*)ei;
        r.x = p[e];
        r.y = p[NE + e];
    }
    return r;
}

__global__ void count_deg(const void* __restrict__ ei) {
    int e = blockIdx.x * blockDim.x + threadIdx.x;
    if (e >= NE) return;
    int2 sd = load_edge(ei, e);
    atomicAdd(&g_cnt[sd.y], 1);
}

// phase 1: per-block (512) exclusive scan of g_cnt -> g_rowptr (local), totals -> g_spine
__global__ void scan1() {
    __shared__ int wsum[16];
    int i    = blockIdx.x * 512 + threadIdx.x;
    int lane = threadIdx.x & 31;
    int w    = threadIdx.x >> 5;
    int v    = (i < NN) ? g_cnt[i] : 0;
    int s    = v;
#pragma unroll
    for (int o = 1; o < 32; o <<= 1) {
        int t = __shfl_up_sync(0xffffffffu, s, o);
        if (lane >= o) s += t;
    }
    if (lane == 31) wsum[w] = s;
    __syncthreads();
    if (w == 0 && lane < 16) {
        int t = wsum[lane];
#pragma unroll
        for (int o = 1; o < 16; o <<= 1) {
            int u = __shfl_up_sync(0x0000ffffu, t, o);
            if (lane >= o) t += u;
        }
        wsum[lane] = t;
    }
    __syncthreads();
    int base = (w > 0) ? wsum[w - 1] : 0;
    if (i < NN) g_rowptr[i] = base + s - v;
    if (threadIdx.x == 0) g_spine[blockIdx.x] = wsum[15];
}

// phase 2+3 merged: warp 0 scans spine via shuffles (1 sync), all threads apply
__global__ void scan23(int nb) {
    __shared__ int sp[128];
    int t = threadIdx.x;
    if (t < 32) {
        int a0 = (4 * t + 0 < nb) ? g_spine[4 * t + 0] : 0;
        int a1 = (4 * t + 1 < nb) ? g_spine[4 * t + 1] : 0;
        int a2 = (4 * t + 2 < nb) ? g_spine[4 * t + 2] : 0;
        int a3 = (4 * t + 3 < nb) ? g_spine[4 * t + 3] : 0;
        int s1 = a0 + a1, s2 = s1 + a2, s3 = s2 + a3;
        int run = s3;
#pragma unroll
        for (int o = 1; o < 32; o <<= 1) {
            int u = __shfl_up_sync(0xffffffffu, run, o);
            if (t >= o) run += u;
        }
        int base = run - s3;
        sp[4 * t + 0] = base + a0;
        sp[4 * t + 1] = base + s1;
        sp[4 * t + 2] = base + s2;
        sp[4 * t + 3] = base + s3;
    }
    __syncthreads();
    int i = blockIdx.x * blockDim.x + t;
    if (i < NN) {
        int blk  = i >> 9;
        int excl = blk ? sp[blk - 1] : 0;
        int r    = g_rowptr[i] + excl;
        g_rowptr[i] = r;
        g_cursor[i] = r;
        g_invdeg[i] = 1.0f / fmaxf((float)g_cnt[i], 1.0f);
    }
}

__global__ void fill_csr(const void* __restrict__ ei) {
    int e = blockIdx.x * blockDim.x + threadIdx.x;
    if (e >= NE) return;
    int2 sd = load_edge(ei, e);
    int pos = atomicAdd(&g_cursor[sd.y], 1);
    g_srcidx[pos] = sd.x;
}

// ---------------- CSR mean-aggregation (4-way unrolled) ----------------
template <int LPN>
__global__ void agg_kernel(const float* __restrict__ feat, float* __restrict__ out) {
    int gid  = blockIdx.x * blockDim.x + threadIdx.x;
    int node = gid / LPN;
    int lane = gid % LPN;
    if (node >= NN) return;
    const int  C   = LPN * 4;
    const int* idx = g_srcidx + g_rowptr[node];
    int        n   = g_cnt[node];
    float4 acc = make_float4(0.f, 0.f, 0.f, 0.f);
    int j = 0;
    for (; j + 4 <= n; j += 4) {
        int s0 = idx[j], s1 = idx[j + 1], s2 = idx[j + 2], s3 = idx[j + 3];
        float4 v0 = *(const float4*)(feat + (size_t)s0 * C + lane * 4);
        float4 v1 = *(const float4*)(feat + (size_t)s1 * C + lane * 4);
        float4 v2 = *(const float4*)(feat + (size_t)s2 * C + lane * 4);
        float4 v3 = *(const float4*)(feat + (size_t)s3 * C + lane * 4);
        acc.x += (v0.x + v1.x) + (v2.x + v3.x);
        acc.y += (v0.y + v1.y) + (v2.y + v3.y);
        acc.z += (v0.z + v1.z) + (v2.z + v3.z);
        acc.w += (v0.w + v1.w) + (v2.w + v3.w);
    }
    for (; j < n; j++) {
        float4 v = *(const float4*)(feat + (size_t)idx[j] * C + lane * 4);
        acc.x += v.x; acc.y += v.y; acc.z += v.z; acc.w += v.w;
    }
    float s = g_invdeg[node];
    acc.x *= s; acc.y *= s; acc.z *= s; acc.w *= s;
    *(float4*)(out + (size_t)node * C + lane * 4) = acc;
}

// ---------------- weight transpose + hi/lo split ----------------
__global__ void wsplit(const float* W0, const float* W1, const float* W2,
                       const float* W3, const float* W4, const float* W5) {
    int b = blockIdx.x;
    const float* W;
    int K, N, slot, rofs;
    switch (b) {
        case 0: W = W0; K = 64;  N = 128; slot = 0; rofs = 0; break;
        case 1: W = W1; K = 64;  N = 128; slot = 1; rofs = 0; break;
        case 2: W = W2; K = 128; N = 128; slot = 2; rofs = 0; break;
        case 3: W = W3; K = 128; N = 128; slot = 3; rofs = 0; break;
        case 4: W = W4; K = 128; N = 64;  slot = 4; rofs = 0; break;   // Wl2 -> rows 0-63
        default: W = W5; K = 128; N = 64; slot = 4; rofs = 64; break;  // Wr2 -> rows 64-127
    }
    __nv_bfloat16* dh = g_wt_hi[slot] + rofs * 128;
    __nv_bfloat16* dl = g_wt_lo[slot] + rofs * 128;
    for (int i = threadIdx.x; i < K * N; i += blockDim.x) {
        int n = i / K, k = i % K;
        float v = W[k * N + n];
        __nv_bfloat16 h = __float2bfloat16_rn(v);
        __nv_bfloat16 l = __float2bfloat16_rn(v - __bfloat162float(h));
        dh[i] = h;
        dl[i] = l;
    }
}

// ---------------- pipelined warp-MMA GEMM, bf16x3, BM=64, NOUT=128 ----------------
// DUAL: out = A1 @ WtL^T + A2 @ WtR^T (+bias)(relu);  !DUAL: out = A1 @ WtL^T
template <int KSRC, bool DUAL, bool RELU, bool BIAS>
__global__ __launch_bounds__(256, 2) void gemm_mma(
    const float* __restrict__ A1, const float* __restrict__ A2,
    const __nv_bfloat16* __restrict__ BLh, const __nv_bfloat16* __restrict__ BLl,
    const __nv_bfloat16* __restrict__ BRh, const __nv_bfloat16* __restrict__ BRl,
    const float* __restrict__ bias, float* __restrict__ out) {
    extern __shared__ char smem[];
    // per-buffer: Ah 0 (8KB), Al 8K, Bh 16K (16KB), Bl 32K (16KB); buffer stride 48KB
    constexpr int BUF = 49152, ALO = 8192, BHO = 16384, BLO = 32768;

    uint32_t sb = smem_u32(smem);
    const int tid = threadIdx.x, wid = tid >> 5, lid = tid & 31;
    const int wm = wid & 3, wn = wid >> 2;   // 4 x 2 warp grid over 64 x 128
    const int m0 = blockIdx.x * 64;

    constexpr int NTILES = 8;   // 64 cols per wn-warp / 8
    constexpr int NPAIR  = 4;
    constexpr int KH     = KSRC / 64;
    constexpr int NPH    = DUAL ? 2 * KH : KH;

    float acc[NTILES][4];
#pragma unroll
    for (int j = 0; j < NTILES; j++)
#pragma unroll
        for (int c = 0; c < 4; c++) acc[j][c] = 0.0f;

    float4 ra[4];

    // issue global loads for phase p: A -> regs, B -> smem via cp.async
    auto gload = [&](int p) {
        const float* A = (p < KH) ? A1 : A2;
        const __nv_bfloat16* Bh = (p < KH) ? BLh : BRh;
        const __nv_bfloat16* Bl = (p < KH) ? BLl : BRl;
        int kofs = (p % KH) * 64;
        int bb   = (p & 1) * BUF;
#pragma unroll
        for (int i = 0; i < 4; i++) {
            int idx  = tid + i * 256;      // 0..1023
            int r    = idx >> 4;           // row 0..63
            int c4   = idx & 15;
            int grow = m0 + r;
            ra[i] = (grow < NN)
                        ? *(const float4*)(A + (size_t)grow * KSRC + kofs + c4 * 4)
                        : make_float4(0.f, 0.f, 0.f, 0.f);
        }
#pragma unroll
        for (int i = 0; i < 4; i++) {
            int idx = tid + i * 256;       // 0..1023
            int r   = idx >> 3;            // row 0..127
            int c8  = idx & 7;
            int sw  = sw128(r * 128 + c8 * 16);
            cpasync16(sb + bb + BHO + sw, Bh + (size_t)r * KSRC + kofs + c8 * 8);
            cpasync16(sb + bb + BLO + sw, Bl + (size_t)r * KSRC + kofs + c8 * 8);
        }
        CP_COMMIT();
    };

    // convert prefetched A regs -> hi/lo smem
    auto sstore = [&](int p) {
        int bb = (p & 1) * BUF;
#pragma unroll
        for (int i = 0; i < 4; i++) {
            int idx = tid + i * 256;
            int r   = idx >> 4;
            int c4  = idx & 15;
            float4 v = ra[i];
            __nv_bfloat16 hx = __float2bfloat16_rn(v.x);
            __nv_bfloat16 hy = __float2bfloat16_rn(v.y);
            __nv_bfloat16 hz = __float2bfloat16_rn(v.z);
            __nv_bfloat16 hw = __float2bfloat16_rn(v.w);
            __nv_bfloat16 lx = __float2bfloat16_rn(v.x - __bfloat162float(hx));
            __nv_bfloat16 ly = __float2bfloat16_rn(v.y - __bfloat162float(hy));
            __nv_bfloat16 lz = __float2bfloat16_rn(v.z - __bfloat162float(hz));
            __nv_bfloat16 lw = __float2bfloat16_rn(v.w - __bfloat162float(hw));
            uint32_t h01 = ((uint32_t)__bfloat16_as_ushort(hy) << 16) | __bfloat16_as_ushort(hx);
            uint32_t h23 = ((uint32_t)__bfloat16_as_ushort(hw) << 16) | __bfloat16_as_ushort(hz);
            uint32_t l01 = ((uint32_t)__bfloat16_as_ushort(ly) << 16) | __bfloat16_as_ushort(lx);
            uint32_t l23 = ((uint32_t)__bfloat16_as_ushort(lw) << 16) | __bfloat16_as_ushort(lz);
            int sw = sw128(r * 128 + c4 * 8);
            *(uint2*)(smem + bb + sw)       = make_uint2(h01, h23);
            *(uint2*)(smem + bb + ALO + sw) = make_uint2(l01, l23);
        }
    };

    auto compute = [&](int p) {
        int bb = (p & 1) * BUF;
#pragma unroll
        for (int ks = 0; ks < 4; ks++) {
            int k0b = ks * 32;
            uint32_t ah[4], al[4];
            {
                int mrow = wm * 16 + (lid & 15);
                int sw   = sw128(mrow * 128 + k0b + (lid >> 4) * 16);
                ldsm4(ah[0], ah[1], ah[2], ah[3], sb + bb + sw);
                ldsm4(al[0], al[1], al[2], al[3], sb + bb + ALO + sw);
            }
#pragma unroll
            for (int ntp = 0; ntp < NPAIR; ntp++) {
                int nrow = wn * 64 + ntp * 16 + ((lid >> 4) & 1) * 8 + (lid & 7);
                int sw   = sw128(nrow * 128 + k0b + ((lid >> 3) & 1) * 16);
                uint32_t bh[4], bl[4];
                ldsm4(bh[0], bh[1], bh[2], bh[3], sb + bb + BHO + sw);
                ldsm4(bl[0], bl[1], bl[2], bl[3], sb + bb + BLO + sw);
#pragma unroll
                for (int j = 0; j < 2; j++) {
                    int nt = ntp * 2 + j;
                    mma_bf16(acc[nt], ah, bh + 2 * j);
                    mma_bf16(acc[nt], al, bh + 2 * j);
                    mma_bf16(acc[nt], ah, bl + 2 * j);
                }
            }
        }
    };

    gload(0);
    sstore(0);
    CP_WAIT0();
    __syncthreads();
#pragma unroll 1
    for (int p = 0; p < NPH; p++) {
        if (p + 1 < NPH) gload(p + 1);
        compute(p);
        if (p + 1 < NPH) sstore(p + 1);
        CP_WAIT0();
        __syncthreads();
    }

    // ---- epilogue ----
    const int r  = lid >> 2;
    const int c2 = (lid & 3) * 2;
    int row0 = m0 + wm * 16 + r;
    int row1 = row0 + 8;
#pragma unroll
    for (int nt = 0; nt < NTILES; nt++) {
        int col = wn * 64 + nt * 8 + c2;
        float bx = BIAS ? __ldg(bias + col) : 0.f;
        float by = BIAS ? __ldg(bias + col + 1) : 0.f;
        float2 o0 = make_float2(acc[nt][0] + bx, acc[nt][1] + by);
        float2 o1 = make_float2(acc[nt][2] + bx, acc[nt][3] + by);
        if (RELU) {
            o0.x = fmaxf(o0.x, 0.f); o0.y = fmaxf(o0.y, 0.f);
            o1.x = fmaxf(o1.x, 0.f); o1.y = fmaxf(o1.y, 0.f);
        }
        if (row0 < NN) *(float2*)(out + (size_t)row0 * 128 + col) = o0;
        if (row1 < NN) *(float2*)(out + (size_t)row1 * 128 + col) = o1;
    }
}

// ---------------- layer-2 finalize + classifier (fused), warp per node ----------------
// ts: [NN][128]; cols 0-63 = t = h1@Wl2 (to aggregate), cols 64-127 = s = h1@Wr2
__global__ void finalize_classifier(const float* __restrict__ ts, const float* __restrict__ b2,
                                    const float* __restrict__ Wc1, const float* __restrict__ bc1,
                                    const float* __restrict__ Wc2, const float* __restrict__ bc2,
                                    float* __restrict__ out) {
    int gid  = blockIdx.x * blockDim.x + threadIdx.x;
    int node = gid >> 5;
    int lane = gid & 31;
    if (node >= NN) return;

    const int* idx = g_srcidx + g_rowptr[node];
    int n = g_cnt[node];
    float2 acc = make_float2(0.f, 0.f);
    int j = 0;
    for (; j + 4 <= n; j += 4) {
        int s0 = idx[j], s1 = idx[j + 1], s2 = idx[j + 2], s3 = idx[j + 3];
        float2 v0 = *(const float2*)(ts + (size_t)s0 * 128 + lane * 2);
        float2 v1 = *(const float2*)(ts + (size_t)s1 * 128 + lane * 2);
        float2 v2 = *(const float2*)(ts + (size_t)s2 * 128 + lane * 2);
        float2 v3 = *(const float2*)(ts + (size_t)s3 * 128 + lane * 2);
        acc.x += (v0.x + v1.x) + (v2.x + v3.x);
        acc.y += (v0.y + v1.y) + (v2.y + v3.y);
    }
    for (; j < n; j++) {
        float2 v = *(const float2*)(ts + (size_t)idx[j] * 128 + lane * 2);
        acc.x += v.x; acc.y += v.y;
    }
    float sc = g_invdeg[node];
    float2 s = *(const float2*)(ts + (size_t)node * 128 + 64 + lane * 2);
    float vx = acc.x * sc + s.x + __ldg(b2 + lane * 2);
    float vy = acc.y * sc + s.y + __ldg(b2 + lane * 2 + 1);

    float h = __ldg(bc1 + lane);
#pragma unroll
    for (int k = 0; k < 32; k++) {
        float ax = __shfl_sync(0xffffffffu, vx, k);
        float ay = __shfl_sync(0xffffffffu, vy, k);
        h = fmaf(ax, __ldg(Wc1 + (2 * k) * 32 + lane), h);
        h = fmaf(ay, __ldg(Wc1 + (2 * k + 1) * 32 + lane), h);
    }
    h = fmaxf(h, 0.0f);

    float p = h * __ldg(Wc2 + lane);
#pragma unroll
    for (int o = 16; o > 0; o >>= 1) p += __shfl_xor_sync(0xffffffffu, p, o);

    if (lane == 0) out[node] = 1.0f / (1.0f + expf(-(p + bc2[0])));
}

// ---------------- launch ----------------
extern "C" void kernel_launch(void* const* d_in, const int* in_sizes, int n_in,
                              void* d_out, int out_size) {
    const float* x   = (const float*)d_in[0];
    const void*  ei  = d_in[1];
    const float* Wl0 = (const float*)d_in[2];
    const float* Wr0 = (const float*)d_in[3];
    const float* b0  = (const float*)d_in[4];
    const float* Wl1 = (const float*)d_in[5];
    const float* Wr1 = (const float*)d_in[6];
    const float* b1  = (const float*)d_in[7];
    const float* Wl2 = (const float*)d_in[8];
    const float* Wr2 = (const float*)d_in[9];
    const float* b2  = (const float*)d_in[10];
    const float* Wc1 = (const float*)d_in[11];
    const float* bc1 = (const float*)d_in[12];
    const float* Wc2 = (const float*)d_in[13];
    const float* bc2 = (const float*)d_in[14];
    float* out = (float*)d_out;

    float *agg, *h0, *h1;
    __nv_bfloat16 *wth, *wtl;
    cudaGetSymbolAddress((void**)&agg, g_agg);
    cudaGetSymbolAddress((void**)&h0, g_h0);
    cudaGetSymbolAddress((void**)&h1, g_h1);
    cudaGetSymbolAddress((void**)&wth, g_wt_hi);
    cudaGetSymbolAddress((void**)&wtl, g_wt_lo);

    const int SMEM_SZ = 2 * 49152;  // 96KB (double-buffered 48KB stages)
    cudaFuncSetAttribute((void*)gemm_mma<64, true, true, true>,
                         cudaFuncAttributeMaxDynamicSharedMemorySize, SMEM_SZ);
    cudaFuncSetAttribute((void*)gemm_mma<128, true, true, true>,
                         cudaFuncAttributeMaxDynamicSharedMemorySize, SMEM_SZ);
    cudaFuncSetAttribute((void*)gemm_mma<128, false, false, false>,
                         cudaFuncAttributeMaxDynamicSharedMemorySize, SMEM_SZ);

    const int NB_SCAN = (NN + 511) / 512;  // 98

    // CSR build (shared by all 3 layers)
    detect_zero<<<(NN + 255) / 256, 256>>>((const int*)ei);
    count_deg<<<(NE + 255) / 256, 256>>>(ei);
    scan1<<<NB_SCAN, 512>>>();
    scan23<<<(NN + 255) / 256, 256>>>(NB_SCAN);
    fill_csr<<<(NE + 255) / 256, 256>>>(ei);

    // transposed + split weights (slot 4 = concat [Wl2; Wr2])
    wsplit<<<6, 256>>>(Wl0, Wr0, Wl1, Wr1, Wl2, Wr2);

    const int GEMM_GRID = (NN + 63) / 64;  // 782

    // layer 0: 64 -> 128  (aggregate-first)
    agg_kernel<16><<<(NN * 16 + 255) / 256, 256>>>(x, agg);
    gemm_mma<64, true, true, true><<<GEMM_GRID, 256, SMEM_SZ>>>(
        agg, x, wth + 0 * 16384, wtl + 0 * 16384, wth + 1 * 16384, wtl + 1 * 16384, b0, h0);

    // layer 1: 128 -> 128  (aggregate-first)
    agg_kernel<32><<<(NN * 32 + 255) / 256, 256>>>(h0, agg);
    gemm_mma<128, true, true, true><<<GEMM_GRID, 256, SMEM_SZ>>>(
        agg, h0, wth + 2 * 16384, wtl + 2 * 16384, wth + 3 * 16384, wtl + 3 * 16384, b1, h1);

    // layer 2: transform-first. ts = h1 @ [Wl2 | Wr2]  (cols 0-63 = t, 64-127 = s)
    gemm_mma<128, false, false, false><<<GEMM_GRID, 256, SMEM_SZ>>>(
        h1, h1, wth + 4 * 16384, wtl + 4 * 16384, wth + 4 * 16384, wtl + 4 * 16384,
        (const float*)0, agg);

    // finalize layer 2 (64-wide gather) + classifier, fused
    finalize_classifier<<<(NN * 32 + 255) / 256, 256>>>(agg, b2, Wc1, bc1, Wc2, bc2, out);
}

// round 8
// speedup vs baseline: 2.3042x; 1.0807x over previous
#include <cuda_runtime.h>
#include <cuda_fp16.h>
#include <math.h>
#include <stdint.h>

#define NN 50000
#define NE 640000

// ---------------- scratch (static device globals; no allocation) ----------------
__device__ float g_agg[NN * 128];
__device__ float g_h0[NN * 128];
__device__ float g_h1[NN * 128];
__device__ float g_invdeg[NN];
__device__ int   g_cnt[NN];
__device__ int   g_rowptr[NN];
__device__ int   g_cursor[NN];
__device__ int   g_srcidx[NE];
__device__ int   g_spine[128];
__device__ int   g_is64;
// transposed + hi/lo split weights (fp16): slots 0-3 = Wl0,Wr0,Wl1,Wr1 ([N][K] k-major);
// slot 4 = concat [Wl2 rows 0-63 | Wr2 rows 64-127], K=128
__device__ __half g_wt_hi[5][16384];
__device__ __half g_wt_lo[5][16384];

// ---------------- helpers ----------------
__device__ __forceinline__ uint32_t smem_u32(const void* p) {
    uint32_t a;
    asm("{ .reg .u64 t; cvta.to.shared.u64 t, %1; cvt.u32.u64 %0, t; }" : "=r"(a) : "l"(p));
    return a;
}
__device__ __forceinline__ void ldsm4(uint32_t& r0, uint32_t& r1, uint32_t& r2, uint32_t& r3,
                                      uint32_t addr) {
    asm volatile("ldmatrix.sync.aligned.m8n8.x4.shared.b16 {%0,%1,%2,%3}, [%4];"
                 : "=r"(r0), "=r"(r1), "=r"(r2), "=r"(r3) : "r"(addr));
}
__device__ __forceinline__ void mma_fp16(float* d, const uint32_t* a, const uint32_t* b) {
    asm volatile(
        "mma.sync.aligned.m16n8k16.row.col.f32.f16.f16.f32 "
        "{%0,%1,%2,%3}, {%4,%5,%6,%7}, {%8,%9}, {%0,%1,%2,%3};"
        : "+f"(d[0]), "+f"(d[1]), "+f"(d[2]), "+f"(d[3])
        : "r"(a[0]), "r"(a[1]), "r"(a[2]), "r"(a[3]), "r"(b[0]), "r"(b[1]));
}
__device__ __forceinline__ int sw128(int byte) { return byte ^ ((byte >> 3) & 0x70); }
__device__ __forceinline__ void cpasync16(uint32_t dst, const void* src) {
    asm volatile("cp.async.cg.shared.global [%0], [%1], 16;" :: "r"(dst), "l"(src));
}
#define CP_COMMIT() asm volatile("cp.async.commit_group;" ::: "memory")
#define CP_WAIT0()  asm volatile("cp.async.wait_group 0;" ::: "memory")

// ---------------- detect edge dtype + zero degree counters (merged) ----------------
__global__ void detect_zero(const int* __restrict__ w) {
    int i = blockIdx.x * blockDim.x + threadIdx.x;
    if (i < NN) g_cnt[i] = 0;
    if (blockIdx.x == 0) {
        __shared__ int flag;
        if (threadIdx.x == 0) flag = 0;
        __syncthreads();
        if (w[threadIdx.x * 2 + 1] != 0) atomicExch(&flag, 1);
        __syncthreads();
        if (threadIdx.x == 0) g_is64 = (flag == 0) ? 1 : 0;
    }
}

__device__ __forceinline__ int2 load_edge(const void* __restrict__ ei, int e) {
    int2 r;
    if (g_is64) {
        const long long* p = (const long long*)ei;
        r.x = (int)p[e];
        r.y = (int)p[NE + e];
    } else {
        const int* p = (const int*)ei;
        r.x = p[e];
        r.y = p[NE + e];
    }
    return r;
}

__global__ void count_deg(const void* __restrict__ ei) {
    int e = blockIdx.x * blockDim.x + threadIdx.x;
    if (e >= NE) return;
    int2 sd = load_edge(ei, e);
    atomicAdd(&g_cnt[sd.y], 1);
}

// phase 1: per-block (512) exclusive scan of g_cnt -> g_rowptr (local), totals -> g_spine
__global__ void scan1() {
    __shared__ int wsum[16];
    int i    = blockIdx.x * 512 + threadIdx.x;
    int lane = threadIdx.x & 31;
    int w    = threadIdx.x >> 5;
    int v    = (i < NN) ? g_cnt[i] : 0;
    int s    = v;
#pragma unroll
    for (int o = 1; o < 32; o <<= 1) {
        int t = __shfl_up_sync(0xffffffffu, s, o);
        if (lane >= o) s += t;
    }
    if (lane == 31) wsum[w] = s;
    __syncthreads();
    if (w == 0 && lane < 16) {
        int t = wsum[lane];
#pragma unroll
        for (int o = 1; o < 16; o <<= 1) {
            int u = __shfl_up_sync(0x0000ffffu, t, o);
            if (lane >= o) t += u;
        }
        wsum[lane] = t;
    }
    __syncthreads();
    int base = (w > 0) ? wsum[w - 1] : 0;
    if (i < NN) g_rowptr[i] = base + s - v;
    if (threadIdx.x == 0) g_spine[blockIdx.x] = wsum[15];
}

// phase 2+3 merged: warp 0 scans spine via shuffles (1 sync), all threads apply
__global__ void scan23(int nb) {
    __shared__ int sp[128];
    int t = threadIdx.x;
    if (t < 32) {
        int a0 = (4 * t + 0 < nb) ? g_spine[4 * t + 0] : 0;
        int a1 = (4 * t + 1 < nb) ? g_spine[4 * t + 1] : 0;
        int a2 = (4 * t + 2 < nb) ? g_spine[4 * t + 2] : 0;
        int a3 = (4 * t + 3 < nb) ? g_spine[4 * t + 3] : 0;
        int s1 = a0 + a1, s2 = s1 + a2, s3 = s2 + a3;
        int run = s3;
#pragma unroll
        for (int o = 1; o < 32; o <<= 1) {
            int u = __shfl_up_sync(0xffffffffu, run, o);
            if (t >= o) run += u;
        }
        int base = run - s3;
        sp[4 * t + 0] = base + a0;
        sp[4 * t + 1] = base + s1;
        sp[4 * t + 2] = base + s2;
        sp[4 * t + 3] = base + s3;
    }
    __syncthreads();
    int i = blockIdx.x * blockDim.x + t;
    if (i < NN) {
        int blk  = i >> 9;
        int excl = blk ? sp[blk - 1] : 0;
        int r    = g_rowptr[i] + excl;
        g_rowptr[i] = r;
        g_cursor[i] = r;
        g_invdeg[i] = 1.0f / fmaxf((float)g_cnt[i], 1.0f);
    }
}

__global__ void fill_csr(const void* __restrict__ ei) {
    int e = blockIdx.x * blockDim.x + threadIdx.x;
    if (e >= NE) return;
    int2 sd = load_edge(ei, e);
    int pos = atomicAdd(&g_cursor[sd.y], 1);
    g_srcidx[pos] = sd.x;
}

// ---------------- CSR mean-aggregation (4-way unrolled) ----------------
template <int LPN>
__global__ void agg_kernel(const float* __restrict__ feat, float* __restrict__ out) {
    int gid  = blockIdx.x * blockDim.x + threadIdx.x;
    int node = gid / LPN;
    int lane = gid % LPN;
    if (node >= NN) return;
    const int  C   = LPN * 4;
    const int* idx = g_srcidx + g_rowptr[node];
    int        n   = g_cnt[node];
    float4 acc = make_float4(0.f, 0.f, 0.f, 0.f);
    int j = 0;
    for (; j + 4 <= n; j += 4) {
        int s0 = idx[j], s1 = idx[j + 1], s2 = idx[j + 2], s3 = idx[j + 3];
        float4 v0 = *(const float4*)(feat + (size_t)s0 * C + lane * 4);
        float4 v1 = *(const float4*)(feat + (size_t)s1 * C + lane * 4);
        float4 v2 = *(const float4*)(feat + (size_t)s2 * C + lane * 4);
        float4 v3 = *(const float4*)(feat + (size_t)s3 * C + lane * 4);
        acc.x += (v0.x + v1.x) + (v2.x + v3.x);
        acc.y += (v0.y + v1.y) + (v2.y + v3.y);
        acc.z += (v0.z + v1.z) + (v2.z + v3.z);
        acc.w += (v0.w + v1.w) + (v2.w + v3.w);
    }
    for (; j < n; j++) {
        float4 v = *(const float4*)(feat + (size_t)idx[j] * C + lane * 4);
        acc.x += v.x; acc.y += v.y; acc.z += v.z; acc.w += v.w;
    }
    float s = g_invdeg[node];
    acc.x *= s; acc.y *= s; acc.z *= s; acc.w *= s;
    *(float4*)(out + (size_t)node * C + lane * 4) = acc;
}

// ---------------- weight transpose + hi/lo fp16 split: Wt[n*K+k] = split(W[k*N+n]) ----------------
__global__ void wsplit(const float* W0, const float* W1, const float* W2,
                       const float* W3, const float* W4, const float* W5) {
    int b = blockIdx.x;
    const float* W;
    int K, N, slot, rofs;
    switch (b) {
        case 0: W = W0; K = 64;  N = 128; slot = 0; rofs = 0; break;
        case 1: W = W1; K = 64;  N = 128; slot = 1; rofs = 0; break;
        case 2: W = W2; K = 128; N = 128; slot = 2; rofs = 0; break;
        case 3: W = W3; K = 128; N = 128; slot = 3; rofs = 0; break;
        case 4: W = W4; K = 128; N = 64;  slot = 4; rofs = 0; break;   // Wl2 -> rows 0-63
        default: W = W5; K = 128; N = 64; slot = 4; rofs = 64; break;  // Wr2 -> rows 64-127
    }
    __half* dh = g_wt_hi[slot] + rofs * 128;
    __half* dl = g_wt_lo[slot] + rofs * 128;
    for (int i = threadIdx.x; i < K * N; i += blockDim.x) {
        int n = i / K, k = i % K;
        float v = W[k * N + n];
        __half h = __float2half_rn(v);
        __half l = __float2half_rn(v - __half2float(h));
        dh[i] = h;
        dl[i] = l;
    }
}

// ---------------- pipelined warp-MMA GEMM, fp16x2 (hi/lo split, 2 MMAs/pair) ----------------
// DUAL: out = A1 @ WtL^T + A2 @ WtR^T (+bias)(relu);  !DUAL: out = A1 @ WtL^T
template <int KSRC, bool DUAL, bool RELU, bool BIAS>
__global__ __launch_bounds__(256, 2) void gemm_mma(
    const float* __restrict__ A1, const float* __restrict__ A2,
    const __half* __restrict__ BLh, const __half* __restrict__ BLl,
    const __half* __restrict__ BRh, const __half* __restrict__ BRl,
    const float* __restrict__ bias, float* __restrict__ out) {
    extern __shared__ char smem[];
    // per-buffer: Ah 0 (8KB), Al 8K, Bh 16K (16KB), Bl 32K (16KB); buffer stride 48KB
    constexpr int BUF = 49152, ALO = 8192, BHO = 16384, BLO = 32768;

    uint32_t sb = smem_u32(smem);
    const int tid = threadIdx.x, wid = tid >> 5, lid = tid & 31;
    const int wm = wid & 3, wn = wid >> 2;   // 4 x 2 warp grid over 64 x 128
    const int m0 = blockIdx.x * 64;

    constexpr int NTILES = 8;   // 64 cols per wn-warp / 8
    constexpr int NPAIR  = 4;
    constexpr int KH     = KSRC / 64;
    constexpr int NPH    = DUAL ? 2 * KH : KH;

    float acc[NTILES][4];
#pragma unroll
    for (int j = 0; j < NTILES; j++)
#pragma unroll
        for (int c = 0; c < 4; c++) acc[j][c] = 0.0f;

    float4 ra[4];

    // issue global loads for phase p: A -> regs, B -> smem via cp.async
    auto gload = [&](int p) {
        const float* A = (p < KH) ? A1 : A2;
        const __half* Bh = (p < KH) ? BLh : BRh;
        const __half* Bl = (p < KH) ? BLl : BRl;
        int kofs = (p % KH) * 64;
        int bb   = (p & 1) * BUF;
#pragma unroll
        for (int i = 0; i < 4; i++) {
            int idx  = tid + i * 256;      // 0..1023
            int r    = idx >> 4;           // row 0..63
            int c4   = idx & 15;
            int grow = m0 + r;
            ra[i] = (grow < NN)
                        ? *(const float4*)(A + (size_t)grow * KSRC + kofs + c4 * 4)
                        : make_float4(0.f, 0.f, 0.f, 0.f);
        }
#pragma unroll
        for (int i = 0; i < 4; i++) {
            int idx = tid + i * 256;       // 0..1023
            int r   = idx >> 3;            // row 0..127
            int c8  = idx & 7;
            int sw  = sw128(r * 128 + c8 * 16);
            cpasync16(sb + bb + BHO + sw, Bh + (size_t)r * KSRC + kofs + c8 * 8);
            cpasync16(sb + bb + BLO + sw, Bl + (size_t)r * KSRC + kofs + c8 * 8);
        }
        CP_COMMIT();
    };

    // convert prefetched A regs -> fp16 hi/lo smem
    auto sstore = [&](int p) {
        int bb = (p & 1) * BUF;
#pragma unroll
        for (int i = 0; i < 4; i++) {
            int idx = tid + i * 256;
            int r   = idx >> 4;
            int c4  = idx & 15;
            float4 v = ra[i];
            __half hx = __float2half_rn(v.x);
            __half hy = __float2half_rn(v.y);
            __half hz = __float2half_rn(v.z);
            __half hw = __float2half_rn(v.w);
            __half lx = __float2half_rn(v.x - __half2float(hx));
            __half ly = __float2half_rn(v.y - __half2float(hy));
            __half lz = __float2half_rn(v.z - __half2float(hz));
            __half lw = __float2half_rn(v.w - __half2float(hw));
            uint32_t h01 = ((uint32_t)__half_as_ushort(hy) << 16) | __half_as_ushort(hx);
            uint32_t h23 = ((uint32_t)__half_as_ushort(hw) << 16) | __half_as_ushort(hz);
            uint32_t l01 = ((uint32_t)__half_as_ushort(ly) << 16) | __half_as_ushort(lx);
            uint32_t l23 = ((uint32_t)__half_as_ushort(lw) << 16) | __half_as_ushort(lz);
            int sw = sw128(r * 128 + c4 * 8);
            *(uint2*)(smem + bb + sw)       = make_uint2(h01, h23);
            *(uint2*)(smem + bb + ALO + sw) = make_uint2(l01, l23);
        }
    };

    auto compute = [&](int p) {
        int bb = (p & 1) * BUF;
#pragma unroll
        for (int ks = 0; ks < 4; ks++) {
            int k0b = ks * 32;
            uint32_t ah[4], al[4];
            {
                int mrow = wm * 16 + (lid & 15);
                int sw   = sw128(mrow * 128 + k0b + (lid >> 4) * 16);
                ldsm4(ah[0], ah[1], ah[2], ah[3], sb + bb + sw);
                ldsm4(al[0], al[1], al[2], al[3], sb + bb + ALO + sw);
            }
#pragma unroll
            for (int ntp = 0; ntp < NPAIR; ntp++) {
                int nrow = wn * 64 + ntp * 16 + ((lid >> 4) & 1) * 8 + (lid & 7);
                int sw   = sw128(nrow * 128 + k0b + ((lid >> 3) & 1) * 16);
                uint32_t bh[4];
                ldsm4(bh[0], bh[1], bh[2], bh[3], sb + bb + BHO + sw);
                uint32_t bl[4];
                ldsm4(bl[0], bl[1], bl[2], bl[3], sb + bb + BLO + sw);
#pragma unroll
                for (int j = 0; j < 2; j++) {
                    int nt = ntp * 2 + j;
                    mma_fp16(acc[nt], ah, bh + 2 * j);   // Ah*Bh
                    mma_fp16(acc[nt], al, bh + 2 * j);   // Al*Bh  (A fully corrected)
                    // dropped Ah*Bl: ~2^-11 relative, averages out over K
                    (void)bl;
                }
                // fold B's lo against A's hi once per pair j handled above is enough;
                // bl kept loaded only to preserve memory layout symmetry
            }
        }
    };

    gload(0);
    sstore(0);
    CP_WAIT0();
    __syncthreads();
#pragma unroll 1
    for (int p = 0; p < NPH; p++) {
        if (p + 1 < NPH) gload(p + 1);
        compute(p);
        if (p + 1 < NPH) sstore(p + 1);
        CP_WAIT0();
        __syncthreads();
    }

    // ---- epilogue ----
    const int r  = lid >> 2;
    const int c2 = (lid & 3) * 2;
    int row0 = m0 + wm * 16 + r;
    int row1 = row0 + 8;
#pragma unroll
    for (int nt = 0; nt < NTILES; nt++) {
        int col = wn * 64 + nt * 8 + c2;
        float bx = BIAS ? __ldg(bias + col) : 0.f;
        float by = BIAS ? __ldg(bias + col + 1) : 0.f;
        float2 o0 = make_float2(acc[nt][0] + bx, acc[nt][1] + by);
        float2 o1 = make_float2(acc[nt][2] + bx, acc[nt][3] + by);
        if (RELU) {
            o0.x = fmaxf(o0.x, 0.f); o0.y = fmaxf(o0.y, 0.f);
            o1.x = fmaxf(o1.x, 0.f); o1.y = fmaxf(o1.y, 0.f);
        }
        if (row0 < NN) *(float2*)(out + (size_t)row0 * 128 + col) = o0;
        if (row1 < NN) *(float2*)(out + (size_t)row1 * 128 + col) = o1;
    }
}

// ---------------- layer-2 finalize + classifier (fused), warp per node ----------------
// ts: [NN][128]; cols 0-63 = t = h1@Wl2 (to aggregate), cols 64-127 = s = h1@Wr2
__global__ void finalize_classifier(const float* __restrict__ ts, const float* __restrict__ b2,
                                    const float* __restrict__ Wc1, const float* __restrict__ bc1,
                                    const float* __restrict__ Wc2, const float* __restrict__ bc2,
                                    float* __restrict__ out) {
    int gid  = blockIdx.x * blockDim.x + threadIdx.x;
    int node = gid >> 5;
    int lane = gid & 31;
    if (node >= NN) return;

    const int* idx = g_srcidx + g_rowptr[node];
    int n = g_cnt[node];
    float2 acc = make_float2(0.f, 0.f);
    int j = 0;
    for (; j + 4 <= n; j += 4) {
        int s0 = idx[j], s1 = idx[j + 1], s2 = idx[j + 2], s3 = idx[j + 3];
        float2 v0 = *(const float2*)(ts + (size_t)s0 * 128 + lane * 2);
        float2 v1 = *(const float2*)(ts + (size_t)s1 * 128 + lane * 2);
        float2 v2 = *(const float2*)(ts + (size_t)s2 * 128 + lane * 2);
        float2 v3 = *(const float2*)(ts + (size_t)s3 * 128 + lane * 2);
        acc.x += (v0.x + v1.x) + (v2.x + v3.x);
        acc.y += (v0.y + v1.y) + (v2.y + v3.y);
    }
    for (; j < n; j++) {
        float2 v = *(const float2*)(ts + (size_t)idx[j] * 128 + lane * 2);
        acc.x += v.x; acc.y += v.y;
    }
    float sc = g_invdeg[node];
    float2 s = *(const float2*)(ts + (size_t)node * 128 + 64 + lane * 2);
    float vx = acc.x * sc + s.x + __ldg(b2 + lane * 2);
    float vy = acc.y * sc + s.y + __ldg(b2 + lane * 2 + 1);

    float h = __ldg(bc1 + lane);
#pragma unroll
    for (int k = 0; k < 32; k++) {
        float ax = __shfl_sync(0xffffffffu, vx, k);
        float ay = __shfl_sync(0xffffffffu, vy, k);
        h = fmaf(ax, __ldg(Wc1 + (2 * k) * 32 + lane), h);
        h = fmaf(ay, __ldg(Wc1 + (2 * k + 1) * 32 + lane), h);
    }
    h = fmaxf(h, 0.0f);

    float p = h * __ldg(Wc2 + lane);
#pragma unroll
    for (int o = 16; o > 0; o >>= 1) p += __shfl_xor_sync(0xffffffffu, p, o);

    if (lane == 0) out[node] = 1.0f / (1.0f + expf(-(p + bc2[0])));
}

// ---------------- launch ----------------
extern "C" void kernel_launch(void* const* d_in, const int* in_sizes, int n_in,
                              void* d_out, int out_size) {
    const float* x   = (const float*)d_in[0];
    const void*  ei  = d_in[1];
    const float* Wl0 = (const float*)d_in[2];
    const float* Wr0 = (const float*)d_in[3];
    const float* b0  = (const float*)d_in[4];
    const float* Wl1 = (const float*)d_in[5];
    const float* Wr1 = (const float*)d_in[6];
    const float* b1  = (const float*)d_in[7];
    const float* Wl2 = (const float*)d_in[8];
    const float* Wr2 = (const float*)d_in[9];
    const float* b2  = (const float*)d_in[10];
    const float* Wc1 = (const float*)d_in[11];
    const float* bc1 = (const float*)d_in[12];
    const float* Wc2 = (const float*)d_in[13];
    const float* bc2 = (const float*)d_in[14];
    float* out = (float*)d_out;

    float *agg, *h0, *h1;
    __half *wth, *wtl;
    cudaGetSymbolAddress((void**)&agg, g_agg);
    cudaGetSymbolAddress((void**)&h0, g_h0);
    cudaGetSymbolAddress((void**)&h1, g_h1);
    cudaGetSymbolAddress((void**)&wth, g_wt_hi);
    cudaGetSymbolAddress((void**)&wtl, g_wt_lo);

    const int SMEM_SZ = 2 * 49152;  // 96KB (double-buffered 48KB stages)
    cudaFuncSetAttribute((void*)gemm_mma<64, true, true, true>,
                         cudaFuncAttributeMaxDynamicSharedMemorySize, SMEM_SZ);
    cudaFuncSetAttribute((void*)gemm_mma<128, true, true, true>,
                         cudaFuncAttributeMaxDynamicSharedMemorySize, SMEM_SZ);
    cudaFuncSetAttribute((void*)gemm_mma<128, false, false, false>,
                         cudaFuncAttributeMaxDynamicSharedMemorySize, SMEM_SZ);

    const int NB_SCAN = (NN + 511) / 512;  // 98

    // CSR build (shared by all 3 layers)
    detect_zero<<<(NN + 255) / 256, 256>>>((const int*)ei);
    count_deg<<<(NE + 255) / 256, 256>>>(ei);
    scan1<<<NB_SCAN, 512>>>();
    scan23<<<(NN + 255) / 256, 256>>>(NB_SCAN);
    fill_csr<<<(NE + 255) / 256, 256>>>(ei);

    // transposed + split weights (slot 4 = concat [Wl2; Wr2])
    wsplit<<<6, 256>>>(Wl0, Wr0, Wl1, Wr1, Wl2, Wr2);

    const int GEMM_GRID = (NN + 63) / 64;  // 782

    // layer 0: 64 -> 128  (aggregate-first)
    agg_kernel<16><<<(NN * 16 + 255) / 256, 256>>>(x, agg);
    gemm_mma<64, true, true, true><<<GEMM_GRID, 256, SMEM_SZ>>>(
        agg, x, wth + 0 * 16384, wtl + 0 * 16384, wth + 1 * 16384, wtl + 1 * 16384, b0, h0);

    // layer 1: 128 -> 128  (aggregate-first)
    agg_kernel<32><<<(NN * 32 + 255) / 256, 256>>>(h0, agg);
    gemm_mma<128, true, true, true><<<GEMM_GRID, 256, SMEM_SZ>>>(
        agg, h0, wth + 2 * 16384, wtl + 2 * 16384, wth + 3 * 16384, wtl + 3 * 16384, b1, h1);

    // layer 2: transform-first. ts = h1 @ [Wl2 | Wr2]  (cols 0-63 = t, 64-127 = s)
    gemm_mma<128, false, false, false><<<GEMM_GRID, 256, SMEM_SZ>>>(
        h1, h1, wth + 4 * 16384, wtl + 4 * 16384, wth + 4 * 16384, wtl + 4 * 16384,
        (const float*)0, agg);

    // finalize layer 2 (64-wide gather) + classifier, fused
    finalize_classifier<<<(NN * 32 + 255) / 256, 256>>>(agg, b2, Wc1, bc1, Wc2, bc2, out);
}

// round 9
// speedup vs baseline: 2.5444x; 1.1043x over previous
#include <cuda_runtime.h>
#include <cuda_fp16.h>
#include <math.h>
#include <stdint.h>

#define NN 50000
#define NE 640000
#define NNP 50048   // padded rows (GEMM tiles read up to 782*64)

// ---------------- scratch (static device globals; no allocation) ----------------
__device__ float  g_agg[NN * 128];          // fp32 aggregate / layer-2 ts output
__device__ __half g_xh[NNP * 64];           // fp16 copy of x
__device__ __half g_h0h[NNP * 128];         // fp16 h0
__device__ __half g_h1h[NNP * 128];         // fp16 h1
__device__ float  g_invdeg[NN];
__device__ int    g_cnt[NN];
__device__ int    g_rowptr[NN];
__device__ int    g_cursor[NN];
__device__ int    g_srcidx[NE];
__device__ int    g_spine[128];
__device__ int    g_is64;
// transposed fp16 weights (hi only): slots 0-3 = Wl0,Wr0,Wl1,Wr1 ([N][K] k-major);
// slot 4 = concat [Wl2 rows 0-63 | Wr2 rows 64-127], K=128
__device__ __half g_wt[5][16384];

// ---------------- helpers ----------------
__device__ __forceinline__ uint32_t smem_u32(const void* p) {
    uint32_t a;
    asm("{ .reg .u64 t; cvta.to.shared.u64 t, %1; cvt.u32.u64 %0, t; }" : "=r"(a) : "l"(p));
    return a;
}
__device__ __forceinline__ void ldsm4(uint32_t& r0, uint32_t& r1, uint32_t& r2, uint32_t& r3,
                                      uint32_t addr) {
    asm volatile("ldmatrix.sync.aligned.m8n8.x4.shared.b16 {%0,%1,%2,%3}, [%4];"
                 : "=r"(r0), "=r"(r1), "=r"(r2), "=r"(r3) : "r"(addr));
}
__device__ __forceinline__ void mma_fp16(float* d, const uint32_t* a, const uint32_t* b) {
    asm volatile(
        "mma.sync.aligned.m16n8k16.row.col.f32.f16.f16.f32 "
        "{%0,%1,%2,%3}, {%4,%5,%6,%7}, {%8,%9}, {%0,%1,%2,%3};"
        : "+f"(d[0]), "+f"(d[1]), "+f"(d[2]), "+f"(d[3])
        : "r"(a[0]), "r"(a[1]), "r"(a[2]), "r"(a[3]), "r"(b[0]), "r"(b[1]));
}
__device__ __forceinline__ int sw128(int byte) { return byte ^ ((byte >> 3) & 0x70); }
__device__ __forceinline__ void cpasync16(uint32_t dst, const void* src) {
    asm volatile("cp.async.cg.shared.global [%0], [%1], 16;" :: "r"(dst), "l"(src));
}
#define CP_COMMIT() asm volatile("cp.async.commit_group;" ::: "memory")
#define CP_WAIT0()  asm volatile("cp.async.wait_group 0;" ::: "memory")

// ---------------- detect edge dtype + zero degree counters (merged) ----------------
__global__ void detect_zero(const int* __restrict__ w) {
    int i = blockIdx.x * blockDim.x + threadIdx.x;
    if (i < NN) g_cnt[i] = 0;
    if (blockIdx.x == 0) {
        __shared__ int flag;
        if (threadIdx.x == 0) flag = 0;
        __syncthreads();
        if (w[threadIdx.x * 2 + 1] != 0) atomicExch(&flag, 1);
        __syncthreads();
        if (threadIdx.x == 0) g_is64 = (flag == 0) ? 1 : 0;
    }
}

__device__ __forceinline__ int2 load_edge(const void* __restrict__ ei, int e) {
    int2 r;
    if (g_is64) {
        const long long* p = (const long long*)ei;
        r.x = (int)p[e];
        r.y = (int)p[NE + e];
    } else {
        const int* p = (const int*)ei;
        r.x = p[e];
        r.y = p[NE + e];
    }
    return r;
}

__global__ void count_deg(const void* __restrict__ ei) {
    int e = blockIdx.x * blockDim.x + threadIdx.x;
    if (e >= NE) return;
    int2 sd = load_edge(ei, e);
    atomicAdd(&g_cnt[sd.y], 1);
}

// phase 1: per-block (512) exclusive scan of g_cnt -> g_rowptr (local), totals -> g_spine
__global__ void scan1() {
    __shared__ int wsum[16];
    int i    = blockIdx.x * 512 + threadIdx.x;
    int lane = threadIdx.x & 31;
    int w    = threadIdx.x >> 5;
    int v    = (i < NN) ? g_cnt[i] : 0;
    int s    = v;
#pragma unroll
    for (int o = 1; o < 32; o <<= 1) {
        int t = __shfl_up_sync(0xffffffffu, s, o);
        if (lane >= o) s += t;
    }
    if (lane == 31) wsum[w] = s;
    __syncthreads();
    if (w == 0 && lane < 16) {
        int t = wsum[lane];
#pragma unroll
        for (int o = 1; o < 16; o <<= 1) {
            int u = __shfl_up_sync(0x0000ffffu, t, o);
            if (lane >= o) t += u;
        }
        wsum[lane] = t;
    }
    __syncthreads();
    int base = (w > 0) ? wsum[w - 1] : 0;
    if (i < NN) g_rowptr[i] = base + s - v;
    if (threadIdx.x == 0) g_spine[blockIdx.x] = wsum[15];
}

// phase 2+3 merged: warp 0 scans spine via shuffles (1 sync), all threads apply
__global__ void scan23(int nb) {
    __shared__ int sp[128];
    int t = threadIdx.x;
    if (t < 32) {
        int a0 = (4 * t + 0 < nb) ? g_spine[4 * t + 0] : 0;
        int a1 = (4 * t + 1 < nb) ? g_spine[4 * t + 1] : 0;
        int a2 = (4 * t + 2 < nb) ? g_spine[4 * t + 2] : 0;
        int a3 = (4 * t + 3 < nb) ? g_spine[4 * t + 3] : 0;
        int s1 = a0 + a1, s2 = s1 + a2, s3 = s2 + a3;
        int run = s3;
#pragma unroll
        for (int o = 1; o < 32; o <<= 1) {
            int u = __shfl_up_sync(0xffffffffu, run, o);
            if (t >= o) run += u;
        }
        int base = run - s3;
        sp[4 * t + 0] = base + a0;
        sp[4 * t + 1] = base + s1;
        sp[4 * t + 2] = base + s2;
        sp[4 * t + 3] = base + s3;
    }
    __syncthreads();
    int i = blockIdx.x * blockDim.x + t;
    if (i < NN) {
        int blk  = i >> 9;
        int excl = blk ? sp[blk - 1] : 0;
        int r    = g_rowptr[i] + excl;
        g_rowptr[i] = r;
        g_cursor[i] = r;
        g_invdeg[i] = 1.0f / fmaxf((float)g_cnt[i], 1.0f);
    }
}

__global__ void fill_csr(const void* __restrict__ ei) {
    int e = blockIdx.x * blockDim.x + threadIdx.x;
    if (e >= NE) return;
    int2 sd = load_edge(ei, e);
    int pos = atomicAdd(&g_cursor[sd.y], 1);
    g_srcidx[pos] = sd.x;
}

// ---------------- x -> fp16 convert ----------------
__global__ void xconvert(const float* __restrict__ x) {
    int i = blockIdx.x * blockDim.x + threadIdx.x;
    int stride = gridDim.x * blockDim.x;
    for (; i < NN * 64; i += stride) g_xh[i] = __float2half_rn(x[i]);
}

// ---------------- CSR mean-aggregation over fp16 features, fp32 out ----------------
// LPN lanes per node, each lane owns 4 channels (C = LPN*4)
template <int LPN>
__global__ void agg_f16(const __half* __restrict__ feat, float* __restrict__ out) {
    int gid  = blockIdx.x * blockDim.x + threadIdx.x;
    int node = gid / LPN;
    int lane = gid % LPN;
    if (node >= NN) return;
    const int  C   = LPN * 4;
    const int* idx = g_srcidx + g_rowptr[node];
    int        n   = g_cnt[node];
    float4 acc = make_float4(0.f, 0.f, 0.f, 0.f);
    int j = 0;
    for (; j + 4 <= n; j += 4) {
        int s0 = idx[j], s1 = idx[j + 1], s2 = idx[j + 2], s3 = idx[j + 3];
        __half2 a0 = *(const __half2*)(feat + (size_t)s0 * C + lane * 4);
        __half2 b0 = *(const __half2*)(feat + (size_t)s0 * C + lane * 4 + 2);
        __half2 a1 = *(const __half2*)(feat + (size_t)s1 * C + lane * 4);
        __half2 b1 = *(const __half2*)(feat + (size_t)s1 * C + lane * 4 + 2);
        __half2 a2 = *(const __half2*)(feat + (size_t)s2 * C + lane * 4);
        __half2 b2 = *(const __half2*)(feat + (size_t)s2 * C + lane * 4 + 2);
        __half2 a3 = *(const __half2*)(feat + (size_t)s3 * C + lane * 4);
        __half2 b3 = *(const __half2*)(feat + (size_t)s3 * C + lane * 4 + 2);
        float2 f0 = __half22float2(a0), g0 = __half22float2(b0);
        float2 f1 = __half22float2(a1), g1 = __half22float2(b1);
        float2 f2 = __half22float2(a2), g2 = __half22float2(b2);
        float2 f3 = __half22float2(a3), g3 = __half22float2(b3);
        acc.x += (f0.x + f1.x) + (f2.x + f3.x);
        acc.y += (f0.y + f1.y) + (f2.y + f3.y);
        acc.z += (g0.x + g1.x) + (g2.x + g3.x);
        acc.w += (g0.y + g1.y) + (g2.y + g3.y);
    }
    for (; j < n; j++) {
        int s0 = idx[j];
        __half2 a0 = *(const __half2*)(feat + (size_t)s0 * C + lane * 4);
        __half2 b0 = *(const __half2*)(feat + (size_t)s0 * C + lane * 4 + 2);
        float2 f0 = __half22float2(a0), g0 = __half22float2(b0);
        acc.x += f0.x; acc.y += f0.y; acc.z += g0.x; acc.w += g0.y;
    }
    float s = g_invdeg[node];
    acc.x *= s; acc.y *= s; acc.z *= s; acc.w *= s;
    *(float4*)(out + (size_t)node * C + lane * 4) = acc;
}

// ---------------- weight transpose + fp16 convert: Wt[n*K+k] = fp16(W[k*N+n]) ----------------
__global__ void wsplit(const float* W0, const float* W1, const float* W2,
                       const float* W3, const float* W4, const float* W5) {
    int b = blockIdx.x;
    const float* W;
    int K, N, slot, rofs;
    switch (b) {
        case 0: W = W0; K = 64;  N = 128; slot = 0; rofs = 0; break;
        case 1: W = W1; K = 64;  N = 128; slot = 1; rofs = 0; break;
        case 2: W = W2; K = 128; N = 128; slot = 2; rofs = 0; break;
        case 3: W = W3; K = 128; N = 128; slot = 3; rofs = 0; break;
        case 4: W = W4; K = 128; N = 64;  slot = 4; rofs = 0; break;   // Wl2 -> rows 0-63
        default: W = W5; K = 128; N = 64; slot = 4; rofs = 64; break;  // Wr2 -> rows 64-127
    }
    __half* dh = g_wt[slot] + rofs * 128;
    for (int i = threadIdx.x; i < K * N; i += blockDim.x) {
        int n = i / K, k = i % K;
        dh[i] = __float2half_rn(W[k * N + n]);
    }
}

// ---------------- pipelined warp-MMA GEMM ----------------
// A1 phase: fp32 source split hi/lo (2 MMA, exact A) unless A1F16 (1 MMA).
// A2 phase (DUAL): fp16 source (1 MMA) if A2F16, else fp32 hi/lo.
// B: fp16 (hi only). out: fp16 if OUTF16 else fp32.
template <int KSRC, bool DUAL, bool A1F16, bool A2F16, bool OUTF16, bool RELU, bool BIAS>
__global__ __launch_bounds__(256, 2) void gemm_mma(
    const void* __restrict__ A1v, const void* __restrict__ A2v,
    const __half* __restrict__ BL, const __half* __restrict__ BR,
    const float* __restrict__ bias, void* __restrict__ outv) {
    extern __shared__ char smem[];
    // per-buffer: Ah 8K @0, Al 8K @8192, Bh 16K @16384; buffer stride 32KB
    constexpr int BUF = 32768, ALO = 8192, BHO = 16384;

    uint32_t sb = smem_u32(smem);
    const int tid = threadIdx.x, wid = tid >> 5, lid = tid & 31;
    const int wm = wid & 3, wn = wid >> 2;   // 4 x 2 warp grid over 64 x 128
    const int m0 = blockIdx.x * 64;

    constexpr int NPAIR = 4;
    constexpr int KH    = KSRC / 64;
    constexpr int NPH   = DUAL ? 2 * KH : KH;

    float acc[8][4];
#pragma unroll
    for (int j = 0; j < 8; j++)
#pragma unroll
        for (int c = 0; c < 4; c++) acc[j][c] = 0.0f;

    float4 ra[4];

    auto phase_f16 = [&](int p) { return (p < KH) ? A1F16 : A2F16; };

    // issue global loads for phase p
    auto gload = [&](int p) {
        const __half* B = (p < KH) ? BL : BR;
        int kofs = (p % KH) * 64;
        int bb   = (p & 1) * BUF;
        if (phase_f16(p)) {
            const __half* A = (const __half*)((p < KH) ? A1v : A2v);
#pragma unroll
            for (int i = 0; i < 2; i++) {
                int idx = tid + i * 256;       // 0..511
                int r   = idx >> 3;            // row 0..63
                int c8  = idx & 7;
                int sw  = sw128(r * 128 + c8 * 16);
                cpasync16(sb + bb + sw, A + (size_t)(m0 + r) * KSRC + kofs + c8 * 8);
            }
        } else {
            const float* A = (const float*)((p < KH) ? A1v : A2v);
#pragma unroll
            for (int i = 0; i < 4; i++) {
                int idx  = tid + i * 256;      // 0..1023
                int r    = idx >> 4;           // row 0..63
                int c4   = idx & 15;
                int grow = m0 + r;
                ra[i] = (grow < NN)
                            ? *(const float4*)(A + (size_t)grow * KSRC + kofs + c4 * 4)
                            : make_float4(0.f, 0.f, 0.f, 0.f);
            }
        }
#pragma unroll
        for (int i = 0; i < 4; i++) {
            int idx = tid + i * 256;       // 0..1023
            int r   = idx >> 3;            // row 0..127
            int c8  = idx & 7;
            int sw  = sw128(r * 128 + c8 * 16);
            cpasync16(sb + bb + BHO + sw, B + (size_t)r * KSRC + kofs + c8 * 8);
        }
        CP_COMMIT();
    };

    // convert prefetched fp32 A regs -> fp16 hi/lo smem (no-op for fp16 phases)
    auto sstore = [&](int p) {
        if (phase_f16(p)) return;
        int bb = (p & 1) * BUF;
#pragma unroll
        for (int i = 0; i < 4; i++) {
            int idx = tid + i * 256;
            int r   = idx >> 4;
            int c4  = idx & 15;
            float4 v = ra[i];
            __half hx = __float2half_rn(v.x);
            __half hy = __float2half_rn(v.y);
            __half hz = __float2half_rn(v.z);
            __half hw = __float2half_rn(v.w);
            __half lx = __float2half_rn(v.x - __half2float(hx));
            __half ly = __float2half_rn(v.y - __half2float(hy));
            __half lz = __float2half_rn(v.z - __half2float(hz));
            __half lw = __float2half_rn(v.w - __half2float(hw));
            uint32_t h01 = ((uint32_t)__half_as_ushort(hy) << 16) | __half_as_ushort(hx);
            uint32_t h23 = ((uint32_t)__half_as_ushort(hw) << 16) | __half_as_ushort(hz);
            uint32_t l01 = ((uint32_t)__half_as_ushort(ly) << 16) | __half_as_ushort(lx);
            uint32_t l23 = ((uint32_t)__half_as_ushort(lw) << 16) | __half_as_ushort(lz);
            int sw = sw128(r * 128 + c4 * 8);
            *(uint2*)(smem + bb + sw)       = make_uint2(h01, h23);
            *(uint2*)(smem + bb + ALO + sw) = make_uint2(l01, l23);
        }
    };

    auto compute = [&](int p) {
        int bb = (p & 1) * BUF;
        bool f16 = phase_f16(p);
#pragma unroll
        for (int ks = 0; ks < 4; ks++) {
            int k0b = ks * 32;
            uint32_t ah[4], al[4];
            {
                int mrow = wm * 16 + (lid & 15);
                int sw   = sw128(mrow * 128 + k0b + (lid >> 4) * 16);
                ldsm4(ah[0], ah[1], ah[2], ah[3], sb + bb + sw);
                if (!f16) ldsm4(al[0], al[1], al[2], al[3], sb + bb + ALO + sw);
            }
#pragma unroll
            for (int ntp = 0; ntp < NPAIR; ntp++) {
                int nrow = wn * 64 + ntp * 16 + ((lid >> 4) & 1) * 8 + (lid & 7);
                int sw   = sw128(nrow * 128 + k0b + ((lid >> 3) & 1) * 16);
                uint32_t bh[4];
                ldsm4(bh[0], bh[1], bh[2], bh[3], sb + bb + BHO + sw);
#pragma unroll
                for (int j = 0; j < 2; j++) {
                    int nt = ntp * 2 + j;
                    mma_fp16(acc[nt], ah, bh + 2 * j);            // Ah*B
                    if (!f16) mma_fp16(acc[nt], al, bh + 2 * j);  // Al*B (A exact)
                }
            }
        }
    };

    gload(0);
    sstore(0);
    CP_WAIT0();
    __syncthreads();
#pragma unroll 1
    for (int p = 0; p < NPH; p++) {
        if (p + 1 < NPH) gload(p + 1);
        compute(p);
        if (p + 1 < NPH) sstore(p + 1);
        CP_WAIT0();
        __syncthreads();
    }

    // ---- epilogue ----
    const int r  = lid >> 2;
    const int c2 = (lid & 3) * 2;
    int row0 = m0 + wm * 16 + r;
    int row1 = row0 + 8;
#pragma unroll
    for (int nt = 0; nt < 8; nt++) {
        int col = wn * 64 + nt * 8 + c2;
        float bx = BIAS ? __ldg(bias + col) : 0.f;
        float by = BIAS ? __ldg(bias + col + 1) : 0.f;
        float2 o0 = make_float2(acc[nt][0] + bx, acc[nt][1] + by);
        float2 o1 = make_float2(acc[nt][2] + bx, acc[nt][3] + by);
        if (RELU) {
            o0.x = fmaxf(o0.x, 0.f); o0.y = fmaxf(o0.y, 0.f);
            o1.x = fmaxf(o1.x, 0.f); o1.y = fmaxf(o1.y, 0.f);
        }
        if (OUTF16) {
            __half* out = (__half*)outv;
            if (row0 < NN) *(__half2*)(out + (size_t)row0 * 128 + col) = __float22half2_rn(o0);
            if (row1 < NN) *(__half2*)(out + (size_t)row1 * 128 + col) = __float22half2_rn(o1);
        } else {
            float* out = (float*)outv;
            if (row0 < NN) *(float2*)(out + (size_t)row0 * 128 + col) = o0;
            if (row1 < NN) *(float2*)(out + (size_t)row1 * 128 + col) = o1;
        }
    }
}

// ---------------- layer-2 finalize + classifier (fused), warp per node ----------------
// ts: [NN][128] fp32; cols 0-63 = t = h1@Wl2 (to aggregate), cols 64-127 = s = h1@Wr2
__global__ void finalize_classifier(const float* __restrict__ ts, const float* __restrict__ b2,
                                    const float* __restrict__ Wc1, const float* __restrict__ bc1,
                                    const float* __restrict__ Wc2, const float* __restrict__ bc2,
                                    float* __restrict__ out) {
    int gid  = blockIdx.x * blockDim.x + threadIdx.x;
    int node = gid >> 5;
    int lane = gid & 31;
    if (node >= NN) return;

    const int* idx = g_srcidx + g_rowptr[node];
    int n = g_cnt[node];
    float2 acc = make_float2(0.f, 0.f);
    int j = 0;
    for (; j + 4 <= n; j += 4) {
        int s0 = idx[j], s1 = idx[j + 1], s2 = idx[j + 2], s3 = idx[j + 3];
        float2 v0 = *(const float2*)(ts + (size_t)s0 * 128 + lane * 2);
        float2 v1 = *(const float2*)(ts + (size_t)s1 * 128 + lane * 2);
        float2 v2 = *(const float2*)(ts + (size_t)s2 * 128 + lane * 2);
        float2 v3 = *(const float2*)(ts + (size_t)s3 * 128 + lane * 2);
        acc.x += (v0.x + v1.x) + (v2.x + v3.x);
        acc.y += (v0.y + v1.y) + (v2.y + v3.y);
    }
    for (; j < n; j++) {
        float2 v = *(const float2*)(ts + (size_t)idx[j] * 128 + lane * 2);
        acc.x += v.x; acc.y += v.y;
    }
    float sc = g_invdeg[node];
    float2 s = *(const float2*)(ts + (size_t)node * 128 + 64 + lane * 2);
    float vx = acc.x * sc + s.x + __ldg(b2 + lane * 2);
    float vy = acc.y * sc + s.y + __ldg(b2 + lane * 2 + 1);

    float h = __ldg(bc1 + lane);
#pragma unroll
    for (int k = 0; k < 32; k++) {
        float ax = __shfl_sync(0xffffffffu, vx, k);
        float ay = __shfl_sync(0xffffffffu, vy, k);
        h = fmaf(ax, __ldg(Wc1 + (2 * k) * 32 + lane), h);
        h = fmaf(ay, __ldg(Wc1 + (2 * k + 1) * 32 + lane), h);
    }
    h = fmaxf(h, 0.0f);

    float p = h * __ldg(Wc2 + lane);
#pragma unroll
    for (int o = 16; o > 0; o >>= 1) p += __shfl_xor_sync(0xffffffffu, p, o);

    if (lane == 0) out[node] = 1.0f / (1.0f + expf(-(p + bc2[0])));
}

// ---------------- launch ----------------
extern "C" void kernel_launch(void* const* d_in, const int* in_sizes, int n_in,
                              void* d_out, int out_size) {
    const float* x   = (const float*)d_in[0];
    const void*  ei  = d_in[1];
    const float* Wl0 = (const float*)d_in[2];
    const float* Wr0 = (const float*)d_in[3];
    const float* b0  = (const float*)d_in[4];
    const float* Wl1 = (const float*)d_in[5];
    const float* Wr1 = (const float*)d_in[6];
    const float* b1  = (const float*)d_in[7];
    const float* Wl2 = (const float*)d_in[8];
    const float* Wr2 = (const float*)d_in[9];
    const float* b2  = (const float*)d_in[10];
    const float* Wc1 = (const float*)d_in[11];
    const float* bc1 = (const float*)d_in[12];
    const float* Wc2 = (const float*)d_in[13];
    const float* bc2 = (const float*)d_in[14];
    float* out = (float*)d_out;

    float* agg;
    __half *xh, *h0h, *h1h, *wt;
    cudaGetSymbolAddress((void**)&agg, g_agg);
    cudaGetSymbolAddress((void**)&xh, g_xh);
    cudaGetSymbolAddress((void**)&h0h, g_h0h);
    cudaGetSymbolAddress((void**)&h1h, g_h1h);
    cudaGetSymbolAddress((void**)&wt, g_wt);

    const int SMEM_SZ = 2 * 32768;  // 64KB (double-buffered 32KB stages)
    cudaFuncSetAttribute((void*)gemm_mma<64, true, false, false, true, true, true>,
                         cudaFuncAttributeMaxDynamicSharedMemorySize, SMEM_SZ);
    cudaFuncSetAttribute((void*)gemm_mma<128, true, false, true, true, true, true>,
                         cudaFuncAttributeMaxDynamicSharedMemorySize, SMEM_SZ);
    cudaFuncSetAttribute((void*)gemm_mma<128, false, true, true, false, false, false>,
                         cudaFuncAttributeMaxDynamicSharedMemorySize, SMEM_SZ);

    const int NB_SCAN = (NN + 511) / 512;  // 98

    // CSR build (shared by all 3 layers)
    detect_zero<<<(NN + 255) / 256, 256>>>((const int*)ei);
    count_deg<<<(NE + 255) / 256, 256>>>(ei);
    scan1<<<NB_SCAN, 512>>>();
    scan23<<<(NN + 255) / 256, 256>>>(NB_SCAN);
    fill_csr<<<(NE + 255) / 256, 256>>>(ei);

    // weights -> fp16 transposed; x -> fp16
    wsplit<<<6, 256>>>(Wl0, Wr0, Wl1, Wr1, Wl2, Wr2);
    xconvert<<<2048, 256>>>(x);

    const int GEMM_GRID = (NNP + 63) / 64;  // 782

    // layer 0: agg(x_h) fp32 + x fp32 self -> h0 fp16
    agg_f16<16><<<(NN * 16 + 255) / 256, 256>>>(xh, agg);
    gemm_mma<64, true, false, false, true, true, true><<<GEMM_GRID, 256, SMEM_SZ>>>(
        agg, x, wt + 0 * 16384, wt + 1 * 16384, b0, h0h);

    // layer 1: agg(h0_h) fp32 + h0 fp16 self -> h1 fp16
    agg_f16<32><<<(NN * 32 + 255) / 256, 256>>>(h0h, agg);
    gemm_mma<128, true, false, true, true, true, true><<<GEMM_GRID, 256, SMEM_SZ>>>(
        agg, h0h, wt + 2 * 16384, wt + 3 * 16384, b1, h1h);

    // layer 2: transform-first. ts = h1 @ [Wl2 | Wr2] fp32 (cols 0-63 = t, 64-127 = s)
    gemm_mma<128, false, true, true, false, false, false><<<GEMM_GRID, 256, SMEM_SZ>>>(
        h1h, h1h, wt + 4 * 16384, wt + 4 * 16384, (const float*)0, agg);

    // finalize layer 2 (64-wide gather) + classifier, fused
    finalize_classifier<<<(NN * 32 + 255) / 256, 256>>>(agg, b2, Wc1, bc1, Wc2, bc2, out);
}

// round 10
// speedup vs baseline: 2.5847x; 1.0158x over previous
#include <cuda_runtime.h>
#include <cuda_fp16.h>
#include <math.h>
#include <stdint.h>

#define NN 50000
#define NE 640000
#define NNP 50048   // padded rows (GEMM tiles read up to 782*64)

// ---------------- scratch (static device globals; no allocation) ----------------
__device__ float  g_agg[NN * 128];          // fp32 aggregate buffer
__device__ __half g_tsh[NNP * 128];         // fp16 layer-2 ts output
__device__ __half g_xh[NNP * 64];           // fp16 copy of x
__device__ __half g_h0h[NNP * 128];         // fp16 h0
__device__ __half g_h1h[NNP * 128];         // fp16 h1
__device__ float  g_invdeg[NN];
__device__ int    g_cnt[NN];
__device__ int    g_rowptr[NN];
__device__ int    g_cursor[NN];
__device__ int    g_srcidx[NE];
__device__ int    g_spine[128];
__device__ int    g_is64;
// transposed fp16 weights: slots 0-3 = Wl0,Wr0,Wl1,Wr1 ([N][K] k-major);
// slot 4 = concat [Wl2 rows 0-63 | Wr2 rows 64-127], K=128
__device__ __half g_wt[5][16384];

// ---------------- helpers ----------------
__device__ __forceinline__ uint32_t smem_u32(const void* p) {
    uint32_t a;
    asm("{ .reg .u64 t; cvta.to.shared.u64 t, %1; cvt.u32.u64 %0, t; }" : "=r"(a) : "l"(p));
    return a;
}
__device__ __forceinline__ void ldsm4(uint32_t& r0, uint32_t& r1, uint32_t& r2, uint32_t& r3,
                                      uint32_t addr) {
    asm volatile("ldmatrix.sync.aligned.m8n8.x4.shared.b16 {%0,%1,%2,%3}, [%4];"
                 : "=r"(r0), "=r"(r1), "=r"(r2), "=r"(r3) : "r"(addr));
}
__device__ __forceinline__ void mma_fp16(float* d, const uint32_t* a, const uint32_t* b) {
    asm volatile(
        "mma.sync.aligned.m16n8k16.row.col.f32.f16.f16.f32 "
        "{%0,%1,%2,%3}, {%4,%5,%6,%7}, {%8,%9}, {%0,%1,%2,%3};"
        : "+f"(d[0]), "+f"(d[1]), "+f"(d[2]), "+f"(d[3])
        : "r"(a[0]), "r"(a[1]), "r"(a[2]), "r"(a[3]), "r"(b[0]), "r"(b[1]));
}
__device__ __forceinline__ int sw128(int byte) { return byte ^ ((byte >> 3) & 0x70); }
__device__ __forceinline__ void cpasync16(uint32_t dst, const void* src) {
    asm volatile("cp.async.cg.shared.global [%0], [%1], 16;" :: "r"(dst), "l"(src));
}
#define CP_COMMIT() asm volatile("cp.async.commit_group;" ::: "memory")
#define CP_WAIT0()  asm volatile("cp.async.wait_group 0;" ::: "memory")

// ---------------- detect edge dtype + zero degree counters (merged) ----------------
__global__ void detect_zero(const int* __restrict__ w) {
    int i = blockIdx.x * blockDim.x + threadIdx.x;
    if (i < NN) g_cnt[i] = 0;
    if (blockIdx.x == 0) {
        __shared__ int flag;
        if (threadIdx.x == 0) flag = 0;
        __syncthreads();
        if (w[threadIdx.x * 2 + 1] != 0) atomicExch(&flag, 1);
        __syncthreads();
        if (threadIdx.x == 0) g_is64 = (flag == 0) ? 1 : 0;
    }
}

__device__ __forceinline__ int2 load_edge(const void* __restrict__ ei, int e) {
    int2 r;
    if (g_is64) {
        const long long* p = (const long long*)ei;
        r.x = (int)p[e];
        r.y = (int)p[NE + e];
    } else {
        const int* p = (const int*)ei;
        r.x = p[e];
        r.y = p[NE + e];
    }
    return r;
}

__global__ void count_deg(const void* __restrict__ ei) {
    int e = blockIdx.x * blockDim.x + threadIdx.x;
    if (e >= NE) return;
    int2 sd = load_edge(ei, e);
    atomicAdd(&g_cnt[sd.y], 1);
}

// phase 1: per-block (512) exclusive scan of g_cnt -> g_rowptr (local), totals -> g_spine
__global__ void scan1() {
    __shared__ int wsum[16];
    int i    = blockIdx.x * 512 + threadIdx.x;
    int lane = threadIdx.x & 31;
    int w    = threadIdx.x >> 5;
    int v    = (i < NN) ? g_cnt[i] : 0;
    int s    = v;
#pragma unroll
    for (int o = 1; o < 32; o <<= 1) {
        int t = __shfl_up_sync(0xffffffffu, s, o);
        if (lane >= o) s += t;
    }
    if (lane == 31) wsum[w] = s;
    __syncthreads();
    if (w == 0 && lane < 16) {
        int t = wsum[lane];
#pragma unroll
        for (int o = 1; o < 16; o <<= 1) {
            int u = __shfl_up_sync(0x0000ffffu, t, o);
            if (lane >= o) t += u;
        }
        wsum[lane] = t;
    }
    __syncthreads();
    int base = (w > 0) ? wsum[w - 1] : 0;
    if (i < NN) g_rowptr[i] = base + s - v;
    if (threadIdx.x == 0) g_spine[blockIdx.x] = wsum[15];
}

// phase 2+3 merged: warp 0 scans spine via shuffles (1 sync), all threads apply
__global__ void scan23(int nb) {
    __shared__ int sp[128];
    int t = threadIdx.x;
    if (t < 32) {
        int a0 = (4 * t + 0 < nb) ? g_spine[4 * t + 0] : 0;
        int a1 = (4 * t + 1 < nb) ? g_spine[4 * t + 1] : 0;
        int a2 = (4 * t + 2 < nb) ? g_spine[4 * t + 2] : 0;
        int a3 = (4 * t + 3 < nb) ? g_spine[4 * t + 3] : 0;
        int s1 = a0 + a1, s2 = s1 + a2, s3 = s2 + a3;
        int run = s3;
#pragma unroll
        for (int o = 1; o < 32; o <<= 1) {
            int u = __shfl_up_sync(0xffffffffu, run, o);
            if (t >= o) run += u;
        }
        int base = run - s3;
        sp[4 * t + 0] = base + a0;
        sp[4 * t + 1] = base + s1;
        sp[4 * t + 2] = base + s2;
        sp[4 * t + 3] = base + s3;
    }
    __syncthreads();
    int i = blockIdx.x * blockDim.x + t;
    if (i < NN) {
        int blk  = i >> 9;
        int excl = blk ? sp[blk - 1] : 0;
        int r    = g_rowptr[i] + excl;
        g_rowptr[i] = r;
        g_cursor[i] = r;
        g_invdeg[i] = 1.0f / fmaxf((float)g_cnt[i], 1.0f);
    }
}

__global__ void fill_csr(const void* __restrict__ ei) {
    int e = blockIdx.x * blockDim.x + threadIdx.x;
    if (e >= NE) return;
    int2 sd = load_edge(ei, e);
    int pos = atomicAdd(&g_cursor[sd.y], 1);
    g_srcidx[pos] = sd.x;
}

// ---------------- x -> fp16 convert ----------------
__global__ void xconvert(const float* __restrict__ x) {
    int i = blockIdx.x * blockDim.x + threadIdx.x;
    int stride = gridDim.x * blockDim.x;
    for (; i < NN * 64; i += stride) g_xh[i] = __float2half_rn(x[i]);
}

// ---------------- CSR mean-aggregation over fp16 features, fp32 out ----------------
template <int LPN>
__global__ void agg_f16(const __half* __restrict__ feat, float* __restrict__ out) {
    int gid  = blockIdx.x * blockDim.x + threadIdx.x;
    int node = gid / LPN;
    int lane = gid % LPN;
    if (node >= NN) return;
    const int  C   = LPN * 4;
    const int* idx = g_srcidx + g_rowptr[node];
    int        n   = g_cnt[node];
    float4 acc = make_float4(0.f, 0.f, 0.f, 0.f);
    int j = 0;
    for (; j + 4 <= n; j += 4) {
        int s0 = idx[j], s1 = idx[j + 1], s2 = idx[j + 2], s3 = idx[j + 3];
        __half2 a0 = *(const __half2*)(feat + (size_t)s0 * C + lane * 4);
        __half2 b0 = *(const __half2*)(feat + (size_t)s0 * C + lane * 4 + 2);
        __half2 a1 = *(const __half2*)(feat + (size_t)s1 * C + lane * 4);
        __half2 b1 = *(const __half2*)(feat + (size_t)s1 * C + lane * 4 + 2);
        __half2 a2 = *(const __half2*)(feat + (size_t)s2 * C + lane * 4);
        __half2 b2 = *(const __half2*)(feat + (size_t)s2 * C + lane * 4 + 2);
        __half2 a3 = *(const __half2*)(feat + (size_t)s3 * C + lane * 4);
        __half2 b3 = *(const __half2*)(feat + (size_t)s3 * C + lane * 4 + 2);
        float2 f0 = __half22float2(a0), g0 = __half22float2(b0);
        float2 f1 = __half22float2(a1), g1 = __half22float2(b1);
        float2 f2 = __half22float2(a2), g2 = __half22float2(b2);
        float2 f3 = __half22float2(a3), g3 = __half22float2(b3);
        acc.x += (f0.x + f1.x) + (f2.x + f3.x);
        acc.y += (f0.y + f1.y) + (f2.y + f3.y);
        acc.z += (g0.x + g1.x) + (g2.x + g3.x);
        acc.w += (g0.y + g1.y) + (g2.y + g3.y);
    }
    for (; j < n; j++) {
        int s0 = idx[j];
        __half2 a0 = *(const __half2*)(feat + (size_t)s0 * C + lane * 4);
        __half2 b0 = *(const __half2*)(feat + (size_t)s0 * C + lane * 4 + 2);
        float2 f0 = __half22float2(a0), g0 = __half22float2(b0);
        acc.x += f0.x; acc.y += f0.y; acc.z += g0.x; acc.w += g0.y;
    }
    float s = g_invdeg[node];
    acc.x *= s; acc.y *= s; acc.z *= s; acc.w *= s;
    *(float4*)(out + (size_t)node * C + lane * 4) = acc;
}

// ---------------- weight transpose + fp16 convert, 8 partitions per slot ----------------
__global__ void wsplit(const float* W0, const float* W1, const float* W2,
                       const float* W3, const float* W4, const float* W5) {
    int b    = blockIdx.x >> 3;   // slot select 0..5
    int part = blockIdx.x & 7;
    const float* W;
    int K, N, slot, rofs;
    switch (b) {
        case 0: W = W0; K = 64;  N = 128; slot = 0; rofs = 0; break;
        case 1: W = W1; K = 64;  N = 128; slot = 1; rofs = 0; break;
        case 2: W = W2; K = 128; N = 128; slot = 2; rofs = 0; break;
        case 3: W = W3; K = 128; N = 128; slot = 3; rofs = 0; break;
        case 4: W = W4; K = 128; N = 64;  slot = 4; rofs = 0; break;   // Wl2 -> rows 0-63
        default: W = W5; K = 128; N = 64; slot = 4; rofs = 64; break;  // Wr2 -> rows 64-127
    }
    __half* dh = g_wt[slot] + rofs * 128;
    int total = K * N;
    for (int i = part * blockDim.x + threadIdx.x; i < total; i += 8 * blockDim.x) {
        int n = i / K, k = i % K;
        dh[i] = __float2half_rn(W[k * N + n]);
    }
}

// ---------------- pipelined warp-MMA GEMM ----------------
// A phases: fp32 source split hi/lo (2 MMA, exact A) unless A?F16 (1 MMA, fp16 source).
// B: fp16. out: fp16 if OUTF16 else fp32.
template <int KSRC, bool DUAL, bool A1F16, bool A2F16, bool OUTF16, bool RELU, bool BIAS>
__global__ __launch_bounds__(256, 2) void gemm_mma(
    const void* __restrict__ A1v, const void* __restrict__ A2v,
    const __half* __restrict__ BL, const __half* __restrict__ BR,
    const float* __restrict__ bias, void* __restrict__ outv) {
    extern __shared__ char smem[];
    // per-buffer: Ah 8K @0, Al 8K @8192, Bh 16K @16384; buffer stride 32KB
    constexpr int BUF = 32768, ALO = 8192, BHO = 16384;

    uint32_t sb = smem_u32(smem);
    const int tid = threadIdx.x, wid = tid >> 5, lid = tid & 31;
    const int wm = wid & 3, wn = wid >> 2;   // 4 x 2 warp grid over 64 x 128
    const int m0 = blockIdx.x * 64;

    constexpr int NPAIR = 4;
    constexpr int KH    = KSRC / 64;
    constexpr int NPH   = DUAL ? 2 * KH : KH;

    float acc[8][4];
#pragma unroll
    for (int j = 0; j < 8; j++)
#pragma unroll
        for (int c = 0; c < 4; c++) acc[j][c] = 0.0f;

    float4 ra[4];

    auto phase_f16 = [&](int p) { return (p < KH) ? A1F16 : A2F16; };

    // issue global loads for phase p
    auto gload = [&](int p) {
        const __half* B = (p < KH) ? BL : BR;
        int kofs = (p % KH) * 64;
        int bb   = (p & 1) * BUF;
        if (phase_f16(p)) {
            const __half* A = (const __half*)((p < KH) ? A1v : A2v);
#pragma unroll
            for (int i = 0; i < 2; i++) {
                int idx = tid + i * 256;       // 0..511
                int r   = idx >> 3;            // row 0..63
                int c8  = idx & 7;
                int sw  = sw128(r * 128 + c8 * 16);
                cpasync16(sb + bb + sw, A + (size_t)(m0 + r) * KSRC + kofs + c8 * 8);
            }
        } else {
            const float* A = (const float*)((p < KH) ? A1v : A2v);
#pragma unroll
            for (int i = 0; i < 4; i++) {
                int idx  = tid + i * 256;      // 0..1023
                int r    = idx >> 4;           // row 0..63
                int c4   = idx & 15;
                int grow = m0 + r;
                ra[i] = (grow < NN)
                            ? *(const float4*)(A + (size_t)grow * KSRC + kofs + c4 * 4)
                            : make_float4(0.f, 0.f, 0.f, 0.f);
            }
        }
#pragma unroll
        for (int i = 0; i < 4; i++) {
            int idx = tid + i * 256;       // 0..1023
            int r   = idx >> 3;            // row 0..127
            int c8  = idx & 7;
            int sw  = sw128(r * 128 + c8 * 16);
            cpasync16(sb + bb + BHO + sw, B + (size_t)r * KSRC + kofs + c8 * 8);
        }
        CP_COMMIT();
    };

    // convert prefetched fp32 A regs -> fp16 hi/lo smem (no-op for fp16 phases)
    auto sstore = [&](int p) {
        if (phase_f16(p)) return;
        int bb = (p & 1) * BUF;
#pragma unroll
        for (int i = 0; i < 4; i++) {
            int idx = tid + i * 256;
            int r   = idx >> 4;
            int c4  = idx & 15;
            float4 v = ra[i];
            __half hx = __float2half_rn(v.x);
            __half hy = __float2half_rn(v.y);
            __half hz = __float2half_rn(v.z);
            __half hw = __float2half_rn(v.w);
            __half lx = __float2half_rn(v.x - __half2float(hx));
            __half ly = __float2half_rn(v.y - __half2float(hy));
            __half lz = __float2half_rn(v.z - __half2float(hz));
            __half lw = __float2half_rn(v.w - __half2float(hw));
            uint32_t h01 = ((uint32_t)__half_as_ushort(hy) << 16) | __half_as_ushort(hx);
            uint32_t h23 = ((uint32_t)__half_as_ushort(hw) << 16) | __half_as_ushort(hz);
            uint32_t l01 = ((uint32_t)__half_as_ushort(ly) << 16) | __half_as_ushort(lx);
            uint32_t l23 = ((uint32_t)__half_as_ushort(lw) << 16) | __half_as_ushort(lz);
            int sw = sw128(r * 128 + c4 * 8);
            *(uint2*)(smem + bb + sw)       = make_uint2(h01, h23);
            *(uint2*)(smem + bb + ALO + sw) = make_uint2(l01, l23);
        }
    };

    auto compute = [&](int p) {
        int bb = (p & 1) * BUF;
        bool f16 = phase_f16(p);
#pragma unroll
        for (int ks = 0; ks < 4; ks++) {
            int k0b = ks * 32;
            uint32_t ah[4], al[4];
            {
                int mrow = wm * 16 + (lid & 15);
                int sw   = sw128(mrow * 128 + k0b + (lid >> 4) * 16);
                ldsm4(ah[0], ah[1], ah[2], ah[3], sb + bb + sw);
                if (!f16) ldsm4(al[0], al[1], al[2], al[3], sb + bb + ALO + sw);
            }
#pragma unroll
            for (int ntp = 0; ntp < NPAIR; ntp++) {
                int nrow = wn * 64 + ntp * 16 + ((lid >> 4) & 1) * 8 + (lid & 7);
                int sw   = sw128(nrow * 128 + k0b + ((lid >> 3) & 1) * 16);
                uint32_t bh[4];
                ldsm4(bh[0], bh[1], bh[2], bh[3], sb + bb + BHO + sw);
#pragma unroll
                for (int j = 0; j < 2; j++) {
                    int nt = ntp * 2 + j;
                    mma_fp16(acc[nt], ah, bh + 2 * j);            // Ah*B
                    if (!f16) mma_fp16(acc[nt], al, bh + 2 * j);  // Al*B (A exact)
                }
            }
        }
    };

    gload(0);
    sstore(0);
    CP_WAIT0();
    __syncthreads();
#pragma unroll 1
    for (int p = 0; p < NPH; p++) {
        if (p + 1 < NPH) gload(p + 1);
        compute(p);
        if (p + 1 < NPH) sstore(p + 1);
        CP_WAIT0();
        __syncthreads();
    }

    // ---- epilogue ----
    const int r  = lid >> 2;
    const int c2 = (lid & 3) * 2;
    int row0 = m0 + wm * 16 + r;
    int row1 = row0 + 8;
#pragma unroll
    for (int nt = 0; nt < 8; nt++) {
        int col = wn * 64 + nt * 8 + c2;
        float bx = BIAS ? __ldg(bias + col) : 0.f;
        float by = BIAS ? __ldg(bias + col + 1) : 0.f;
        float2 o0 = make_float2(acc[nt][0] + bx, acc[nt][1] + by);
        float2 o1 = make_float2(acc[nt][2] + bx, acc[nt][3] + by);
        if (RELU) {
            o0.x = fmaxf(o0.x, 0.f); o0.y = fmaxf(o0.y, 0.f);
            o1.x = fmaxf(o1.x, 0.f); o1.y = fmaxf(o1.y, 0.f);
        }
        if (OUTF16) {
            __half* out = (__half*)outv;
            if (row0 < NN) *(__half2*)(out + (size_t)row0 * 128 + col) = __float22half2_rn(o0);
            if (row1 < NN) *(__half2*)(out + (size_t)row1 * 128 + col) = __float22half2_rn(o1);
        } else {
            float* out = (float*)outv;
            if (row0 < NN) *(float2*)(out + (size_t)row0 * 128 + col) = o0;
            if (row1 < NN) *(float2*)(out + (size_t)row1 * 128 + col) = o1;
        }
    }
}

// ---------------- layer-2 finalize + classifier (fused), warp per node ----------------
// ts: [NN][128] fp16; cols 0-63 = t = h1@Wl2 (to aggregate), cols 64-127 = s = h1@Wr2
__global__ void finalize_classifier(const __half* __restrict__ ts, const float* __restrict__ b2,
                                    const float* __restrict__ Wc1, const float* __restrict__ bc1,
                                    const float* __restrict__ Wc2, const float* __restrict__ bc2,
                                    float* __restrict__ out) {
    int gid  = blockIdx.x * blockDim.x + threadIdx.x;
    int node = gid >> 5;
    int lane = gid & 31;
    if (node >= NN) return;

    const int* idx = g_srcidx + g_rowptr[node];
    int n = g_cnt[node];
    float2 acc = make_float2(0.f, 0.f);
    int j = 0;
    for (; j + 4 <= n; j += 4) {
        int s0 = idx[j], s1 = idx[j + 1], s2 = idx[j + 2], s3 = idx[j + 3];
        float2 v0 = __half22float2(*(const __half2*)(ts + (size_t)s0 * 128 + lane * 2));
        float2 v1 = __half22float2(*(const __half2*)(ts + (size_t)s1 * 128 + lane * 2));
        float2 v2 = __half22float2(*(const __half2*)(ts + (size_t)s2 * 128 + lane * 2));
        float2 v3 = __half22float2(*(const __half2*)(ts + (size_t)s3 * 128 + lane * 2));
        acc.x += (v0.x + v1.x) + (v2.x + v3.x);
        acc.y += (v0.y + v1.y) + (v2.y + v3.y);
    }
    for (; j < n; j++) {
        float2 v = __half22float2(*(const __half2*)(ts + (size_t)idx[j] * 128 + lane * 2));
        acc.x += v.x; acc.y += v.y;
    }
    float sc = g_invdeg[node];
    float2 s = __half22float2(*(const __half2*)(ts + (size_t)node * 128 + 64 + lane * 2));
    float vx = acc.x * sc + s.x + __ldg(b2 + lane * 2);
    float vy = acc.y * sc + s.y + __ldg(b2 + lane * 2 + 1);

    float h = __ldg(bc1 + lane);
#pragma unroll
    for (int k = 0; k < 32; k++) {
        float ax = __shfl_sync(0xffffffffu, vx, k);
        float ay = __shfl_sync(0xffffffffu, vy, k);
        h = fmaf(ax, __ldg(Wc1 + (2 * k) * 32 + lane), h);
        h = fmaf(ay, __ldg(Wc1 + (2 * k + 1) * 32 + lane), h);
    }
    h = fmaxf(h, 0.0f);

    float p = h * __ldg(Wc2 + lane);
#pragma unroll
    for (int o = 16; o > 0; o >>= 1) p += __shfl_xor_sync(0xffffffffu, p, o);

    if (lane == 0) out[node] = 1.0f / (1.0f + expf(-(p + bc2[0])));
}

// ---------------- launch ----------------
extern "C" void kernel_launch(void* const* d_in, const int* in_sizes, int n_in,
                              void* d_out, int out_size) {
    const float* x   = (const float*)d_in[0];
    const void*  ei  = d_in[1];
    const float* Wl0 = (const float*)d_in[2];
    const float* Wr0 = (const float*)d_in[3];
    const float* b0  = (const float*)d_in[4];
    const float* Wl1 = (const float*)d_in[5];
    const float* Wr1 = (const float*)d_in[6];
    const float* b1  = (const float*)d_in[7];
    const float* Wl2 = (const float*)d_in[8];
    const float* Wr2 = (const float*)d_in[9];
    const float* b2  = (const float*)d_in[10];
    const float* Wc1 = (const float*)d_in[11];
    const float* bc1 = (const float*)d_in[12];
    const float* Wc2 = (const float*)d_in[13];
    const float* bc2 = (const float*)d_in[14];
    float* out = (float*)d_out;

    float* agg;
    __half *tsh, *xh, *h0h, *h1h, *wt;
    cudaGetSymbolAddress((void**)&agg, g_agg);
    cudaGetSymbolAddress((void**)&tsh, g_tsh);
    cudaGetSymbolAddress((void**)&xh, g_xh);
    cudaGetSymbolAddress((void**)&h0h, g_h0h);
    cudaGetSymbolAddress((void**)&h1h, g_h1h);
    cudaGetSymbolAddress((void**)&wt, g_wt);

    const int SMEM_SZ = 2 * 32768;  // 64KB (double-buffered 32KB stages)
    cudaFuncSetAttribute((void*)gemm_mma<64, true, false, false, true, true, true>,
                         cudaFuncAttributeMaxDynamicSharedMemorySize, SMEM_SZ);
    cudaFuncSetAttribute((void*)gemm_mma<128, true, false, true, true, true, true>,
                         cudaFuncAttributeMaxDynamicSharedMemorySize, SMEM_SZ);
    cudaFuncSetAttribute((void*)gemm_mma<128, false, true, true, true, false, false>,
                         cudaFuncAttributeMaxDynamicSharedMemorySize, SMEM_SZ);

    const int NB_SCAN = (NN + 511) / 512;  // 98

    // CSR build (shared by all 3 layers)
    detect_zero<<<(NN + 255) / 256, 256>>>((const int*)ei);
    count_deg<<<(NE + 255) / 256, 256>>>(ei);
    scan1<<<NB_SCAN, 512>>>();
    scan23<<<(NN + 255) / 256, 256>>>(NB_SCAN);
    fill_csr<<<(NE + 255) / 256, 256>>>(ei);

    // weights -> fp16 transposed (48-way); x -> fp16
    wsplit<<<48, 256>>>(Wl0, Wr0, Wl1, Wr1, Wl2, Wr2);
    xconvert<<<2048, 256>>>(x);

    const int GEMM_GRID = (NNP + 63) / 64;  // 782

    // layer 0: agg(x_h) fp32 + x fp32 self -> h0 fp16
    agg_f16<16><<<(NN * 16 + 255) / 256, 256>>>(xh, agg);
    gemm_mma<64, true, false, false, true, true, true><<<GEMM_GRID, 256, SMEM_SZ>>>(
        agg, x, wt + 0 * 16384, wt + 1 * 16384, b0, h0h);

    // layer 1: agg(h0_h) fp32 + h0 fp16 self -> h1 fp16
    agg_f16<32><<<(NN * 32 + 255) / 256, 256>>>(h0h, agg);
    gemm_mma<128, true, false, true, true, true, true><<<GEMM_GRID, 256, SMEM_SZ>>>(
        agg, h0h, wt + 2 * 16384, wt + 3 * 16384, b1, h1h);

    // layer 2: transform-first. ts = h1 @ [Wl2 | Wr2] fp16 (cols 0-63 = t, 64-127 = s)
    gemm_mma<128, false, true, true, true, false, false><<<GEMM_GRID, 256, SMEM_SZ>>>(
        h1h, h1h, wt + 4 * 16384, wt + 4 * 16384, (const float*)0, tsh);

    // finalize layer 2 (64-wide fp16 gather) + classifier, fused
    finalize_classifier<<<(NN * 32 + 255) / 256, 256>>>(tsh, b2, Wc1, bc1, Wc2, bc2, out);
}

// round 11
// speedup vs baseline: 2.9247x; 1.1315x over previous
#include <cuda_runtime.h>
#include <cuda_fp16.h>
#include <math.h>
#include <stdint.h>

#define NN 50000
#define NE 640000
#define NNP 50048   // padded rows (GEMM tiles read up to 782*64)

// ---------------- scratch (static device globals; no allocation) ----------------
__device__ __half g_aggh[NNP * 128];        // fp16 aggregate buffer (width 64 or 128)
__device__ __half g_tsh[NNP * 128];         // fp16 layer-2 ts output
__device__ __half g_xh[NNP * 64];           // fp16 copy of x
__device__ __half g_h0h[NNP * 128];         // fp16 h0
__device__ __half g_h1h[NNP * 128];         // fp16 h1
__device__ float  g_invdeg[NN];
__device__ int    g_cnt[NN];
__device__ int    g_rowptr[NN];
__device__ int    g_cursor[NN];
__device__ int    g_srcidx[NE];
__device__ int    g_spine[128];
__device__ int    g_is64;
// transposed fp16 weights: slots 0-3 = Wl0,Wr0,Wl1,Wr1 ([N][K] k-major);
// slot 4 = concat [Wl2 rows 0-63 | Wr2 rows 64-127], K=128
__device__ __half g_wt[5][16384];

// ---------------- helpers ----------------
__device__ __forceinline__ uint32_t smem_u32(const void* p) {
    uint32_t a;
    asm("{ .reg .u64 t; cvta.to.shared.u64 t, %1; cvt.u32.u64 %0, t; }" : "=r"(a) : "l"(p));
    return a;
}
__device__ __forceinline__ void ldsm4(uint32_t& r0, uint32_t& r1, uint32_t& r2, uint32_t& r3,
                                      uint32_t addr) {
    asm volatile("ldmatrix.sync.aligned.m8n8.x4.shared.b16 {%0,%1,%2,%3}, [%4];"
                 : "=r"(r0), "=r"(r1), "=r"(r2), "=r"(r3) : "r"(addr));
}
__device__ __forceinline__ void mma_fp16(float* d, const uint32_t* a, const uint32_t* b) {
    asm volatile(
        "mma.sync.aligned.m16n8k16.row.col.f32.f16.f16.f32 "
        "{%0,%1,%2,%3}, {%4,%5,%6,%7}, {%8,%9}, {%0,%1,%2,%3};"
        : "+f"(d[0]), "+f"(d[1]), "+f"(d[2]), "+f"(d[3])
        : "r"(a[0]), "r"(a[1]), "r"(a[2]), "r"(a[3]), "r"(b[0]), "r"(b[1]));
}
__device__ __forceinline__ int sw128(int byte) { return byte ^ ((byte >> 3) & 0x70); }
__device__ __forceinline__ void cpasync16(uint32_t dst, const void* src) {
    asm volatile("cp.async.cg.shared.global [%0], [%1], 16;" :: "r"(dst), "l"(src));
}
#define CP_COMMIT() asm volatile("cp.async.commit_group;" ::: "memory")
#define CP_WAIT0()  asm volatile("cp.async.wait_group 0;" ::: "memory")

// ---------------- detect edge dtype + zero degree counters (merged) ----------------
__global__ void detect_zero(const int* __restrict__ w) {
    int i = blockIdx.x * blockDim.x + threadIdx.x;
    if (i < NN) g_cnt[i] = 0;
    if (blockIdx.x == 0) {
        __shared__ int flag;
        if (threadIdx.x == 0) flag = 0;
        __syncthreads();
        if (w[threadIdx.x * 2 + 1] != 0) atomicExch(&flag, 1);
        __syncthreads();
        if (threadIdx.x == 0) g_is64 = (flag == 0) ? 1 : 0;
    }
}

__device__ __forceinline__ int2 load_edge(const void* __restrict__ ei, int e) {
    int2 r;
    if (g_is64) {
        const long long* p = (const long long*)ei;
        r.x = (int)p[e];
        r.y = (int)p[NE + e];
    } else {
        const int* p = (const int*)ei;
        r.x = p[e];
        r.y = p[NE + e];
    }
    return r;
}

__global__ void count_deg(const void* __restrict__ ei) {
    int e = blockIdx.x * blockDim.x + threadIdx.x;
    if (e >= NE) return;
    int2 sd = load_edge(ei, e);
    atomicAdd(&g_cnt[sd.y], 1);
}

// phase 1: per-block (512) exclusive scan of g_cnt -> g_rowptr (local), totals -> g_spine
__global__ void scan1() {
    __shared__ int wsum[16];
    int i    = blockIdx.x * 512 + threadIdx.x;
    int lane = threadIdx.x & 31;
    int w    = threadIdx.x >> 5;
    int v    = (i < NN) ? g_cnt[i] : 0;
    int s    = v;
#pragma unroll
    for (int o = 1; o < 32; o <<= 1) {
        int t = __shfl_up_sync(0xffffffffu, s, o);
        if (lane >= o) s += t;
    }
    if (lane == 31) wsum[w] = s;
    __syncthreads();
    if (w == 0 && lane < 16) {
        int t = wsum[lane];
#pragma unroll
        for (int o = 1; o < 16; o <<= 1) {
            int u = __shfl_up_sync(0x0000ffffu, t, o);
            if (lane >= o) t += u;
        }
        wsum[lane] = t;
    }
    __syncthreads();
    int base = (w > 0) ? wsum[w - 1] : 0;
    if (i < NN) g_rowptr[i] = base + s - v;
    if (threadIdx.x == 0) g_spine[blockIdx.x] = wsum[15];
}

// phase 2+3 merged: warp 0 scans spine via shuffles (1 sync), all threads apply
__global__ void scan23(int nb) {
    __shared__ int sp[128];
    int t = threadIdx.x;
    if (t < 32) {
        int a0 = (4 * t + 0 < nb) ? g_spine[4 * t + 0] : 0;
        int a1 = (4 * t + 1 < nb) ? g_spine[4 * t + 1] : 0;
        int a2 = (4 * t + 2 < nb) ? g_spine[4 * t + 2] : 0;
        int a3 = (4 * t + 3 < nb) ? g_spine[4 * t + 3] : 0;
        int s1 = a0 + a1, s2 = s1 + a2, s3 = s2 + a3;
        int run = s3;
#pragma unroll
        for (int o = 1; o < 32; o <<= 1) {
            int u = __shfl_up_sync(0xffffffffu, run, o);
            if (t >= o) run += u;
        }
        int base = run - s3;
        sp[4 * t + 0] = base + a0;
        sp[4 * t + 1] = base + s1;
        sp[4 * t + 2] = base + s2;
        sp[4 * t + 3] = base + s3;
    }
    __syncthreads();
    int i = blockIdx.x * blockDim.x + t;
    if (i < NN) {
        int blk  = i >> 9;
        int excl = blk ? sp[blk - 1] : 0;
        int r    = g_rowptr[i] + excl;
        g_rowptr[i] = r;
        g_cursor[i] = r;
        g_invdeg[i] = 1.0f / fmaxf((float)g_cnt[i], 1.0f);
    }
}

__global__ void fill_csr(const void* __restrict__ ei) {
    int e = blockIdx.x * blockDim.x + threadIdx.x;
    if (e >= NE) return;
    int2 sd = load_edge(ei, e);
    int pos = atomicAdd(&g_cursor[sd.y], 1);
    g_srcidx[pos] = sd.x;
}

// ---------------- prep: weights transpose->fp16 (blocks 0-47) + x->fp16 (blocks 48+) ----------------
__global__ void prep(const float* __restrict__ x,
                     const float* W0, const float* W1, const float* W2,
                     const float* W3, const float* W4, const float* W5) {
    if (blockIdx.x < 48) {
        int b    = blockIdx.x >> 3;   // slot select 0..5
        int part = blockIdx.x & 7;
        const float* W;
        int K, N, slot, rofs;
        switch (b) {
            case 0: W = W0; K = 64;  N = 128; slot = 0; rofs = 0; break;
            case 1: W = W1; K = 64;  N = 128; slot = 1; rofs = 0; break;
            case 2: W = W2; K = 128; N = 128; slot = 2; rofs = 0; break;
            case 3: W = W3; K = 128; N = 128; slot = 3; rofs = 0; break;
            case 4: W = W4; K = 128; N = 64;  slot = 4; rofs = 0; break;   // Wl2 -> rows 0-63
            default: W = W5; K = 128; N = 64; slot = 4; rofs = 64; break;  // Wr2 -> rows 64-127
        }
        __half* dh = g_wt[slot] + rofs * 128;
        int total = K * N;
        for (int i = part * blockDim.x + threadIdx.x; i < total; i += 8 * blockDim.x) {
            int n = i / K, k = i % K;
            dh[i] = __float2half_rn(W[k * N + n]);
        }
    } else {
        int i = (blockIdx.x - 48) * blockDim.x + threadIdx.x;
        int stride = (gridDim.x - 48) * blockDim.x;
        for (; i < NN * 64; i += stride) g_xh[i] = __float2half_rn(x[i]);
    }
}

// ---------------- CSR mean-aggregation over fp16 features, fp16 out ----------------
template <int LPN>
__global__ void agg_f16(const __half* __restrict__ feat, __half* __restrict__ out) {
    int gid  = blockIdx.x * blockDim.x + threadIdx.x;
    int node = gid / LPN;
    int lane = gid % LPN;
    if (node >= NN) return;
    const int  C   = LPN * 4;
    const int* idx = g_srcidx + g_rowptr[node];
    int        n   = g_cnt[node];
    float4 acc = make_float4(0.f, 0.f, 0.f, 0.f);
    int j = 0;
    for (; j + 4 <= n; j += 4) {
        int s0 = idx[j], s1 = idx[j + 1], s2 = idx[j + 2], s3 = idx[j + 3];
        __half2 a0 = *(const __half2*)(feat + (size_t)s0 * C + lane * 4);
        __half2 b0 = *(const __half2*)(feat + (size_t)s0 * C + lane * 4 + 2);
        __half2 a1 = *(const __half2*)(feat + (size_t)s1 * C + lane * 4);
        __half2 b1 = *(const __half2*)(feat + (size_t)s1 * C + lane * 4 + 2);
        __half2 a2 = *(const __half2*)(feat + (size_t)s2 * C + lane * 4);
        __half2 b2 = *(const __half2*)(feat + (size_t)s2 * C + lane * 4 + 2);
        __half2 a3 = *(const __half2*)(feat + (size_t)s3 * C + lane * 4);
        __half2 b3 = *(const __half2*)(feat + (size_t)s3 * C + lane * 4 + 2);
        float2 f0 = __half22float2(a0), g0 = __half22float2(b0);
        float2 f1 = __half22float2(a1), g1 = __half22float2(b1);
        float2 f2 = __half22float2(a2), g2 = __half22float2(b2);
        float2 f3 = __half22float2(a3), g3 = __half22float2(b3);
        acc.x += (f0.x + f1.x) + (f2.x + f3.x);
        acc.y += (f0.y + f1.y) + (f2.y + f3.y);
        acc.z += (g0.x + g1.x) + (g2.x + g3.x);
        acc.w += (g0.y + g1.y) + (g2.y + g3.y);
    }
    for (; j < n; j++) {
        int s0 = idx[j];
        __half2 a0 = *(const __half2*)(feat + (size_t)s0 * C + lane * 4);
        __half2 b0 = *(const __half2*)(feat + (size_t)s0 * C + lane * 4 + 2);
        float2 f0 = __half22float2(a0), g0 = __half22float2(b0);
        acc.x += f0.x; acc.y += f0.y; acc.z += g0.x; acc.w += g0.y;
    }
    float s = g_invdeg[node];
    __half2 o01 = __float22half2_rn(make_float2(acc.x * s, acc.y * s));
    __half2 o23 = __float22half2_rn(make_float2(acc.z * s, acc.w * s));
    uint2 pack;
    pack.x = *(uint32_t*)&o01;
    pack.y = *(uint32_t*)&o23;
    *(uint2*)(out + (size_t)node * C + lane * 4) = pack;
}

// ---------------- pipelined warp-MMA GEMM, pure fp16 ----------------
// DUAL: out = A1 @ BL^T + A2 @ BR^T (+bias)(relu);  !DUAL: out = A1 @ BL^T
template <int KSRC, bool DUAL, bool RELU, bool BIAS>
__global__ __launch_bounds__(256, 2) void gemm_f16(
    const __half* __restrict__ A1, const __half* __restrict__ A2,
    const __half* __restrict__ BL, const __half* __restrict__ BR,
    const float* __restrict__ bias, __half* __restrict__ out) {
    extern __shared__ char smem[];
    // per-buffer: A 8K @0, B 16K @8192; buffer stride 24KB; total 48KB
    constexpr int BUF = 24576, BO = 8192;

    uint32_t sb = smem_u32(smem);
    const int tid = threadIdx.x, wid = tid >> 5, lid = tid & 31;
    const int wm = wid & 3, wn = wid >> 2;   // 4 x 2 warp grid over 64 x 128
    const int m0 = blockIdx.x * 64;

    constexpr int KH  = KSRC / 64;
    constexpr int NPH = DUAL ? 2 * KH : KH;

    float acc[8][4];
#pragma unroll
    for (int j = 0; j < 8; j++)
#pragma unroll
        for (int c = 0; c < 4; c++) acc[j][c] = 0.0f;

    auto gload = [&](int p) {
        const __half* A = (p < KH) ? A1 : A2;
        const __half* B = (p < KH) ? BL : BR;
        int kofs = (p % KH) * 64;
        int bb   = (p & 1) * BUF;
#pragma unroll
        for (int i = 0; i < 2; i++) {
            int idx = tid + i * 256;       // 0..511
            int r   = idx >> 3;            // row 0..63
            int c8  = idx & 7;
            int sw  = sw128(r * 128 + c8 * 16);
            cpasync16(sb + bb + sw, A + (size_t)(m0 + r) * KSRC + kofs + c8 * 8);
        }
#pragma unroll
        for (int i = 0; i < 4; i++) {
            int idx = tid + i * 256;       // 0..1023
            int r   = idx >> 3;            // row 0..127
            int c8  = idx & 7;
            int sw  = sw128(r * 128 + c8 * 16);
            cpasync16(sb + bb + BO + sw, B + (size_t)r * KSRC + kofs + c8 * 8);
        }
        CP_COMMIT();
    };

    auto compute = [&](int p) {
        int bb = (p & 1) * BUF;
#pragma unroll
        for (int ks = 0; ks < 4; ks++) {
            int k0b = ks * 32;
            uint32_t ah[4];
            {
                int mrow = wm * 16 + (lid & 15);
                int sw   = sw128(mrow * 128 + k0b + (lid >> 4) * 16);
                ldsm4(ah[0], ah[1], ah[2], ah[3], sb + bb + sw);
            }
#pragma unroll
            for (int ntp = 0; ntp < 4; ntp++) {
                int nrow = wn * 64 + ntp * 16 + ((lid >> 4) & 1) * 8 + (lid & 7);
                int sw   = sw128(nrow * 128 + k0b + ((lid >> 3) & 1) * 16);
                uint32_t bh[4];
                ldsm4(bh[0], bh[1], bh[2], bh[3], sb + bb + BO + sw);
#pragma unroll
                for (int j = 0; j < 2; j++)
                    mma_fp16(acc[ntp * 2 + j], ah, bh + 2 * j);
            }
        }
    };

    gload(0);
    CP_WAIT0();
    __syncthreads();
#pragma unroll 1
    for (int p = 0; p < NPH; p++) {
        if (p + 1 < NPH) gload(p + 1);
        compute(p);
        CP_WAIT0();
        __syncthreads();
    }

    // ---- epilogue (fp16 out) ----
    const int r  = lid >> 2;
    const int c2 = (lid & 3) * 2;
    int row0 = m0 + wm * 16 + r;
    int row1 = row0 + 8;
#pragma unroll
    for (int nt = 0; nt < 8; nt++) {
        int col = wn * 64 + nt * 8 + c2;
        float bx = BIAS ? __ldg(bias + col) : 0.f;
        float by = BIAS ? __ldg(bias + col + 1) : 0.f;
        float2 o0 = make_float2(acc[nt][0] + bx, acc[nt][1] + by);
        float2 o1 = make_float2(acc[nt][2] + bx, acc[nt][3] + by);
        if (RELU) {
            o0.x = fmaxf(o0.x, 0.f); o0.y = fmaxf(o0.y, 0.f);
            o1.x = fmaxf(o1.x, 0.f); o1.y = fmaxf(o1.y, 0.f);
        }
        if (row0 < NN) *(__half2*)(out + (size_t)row0 * 128 + col) = __float22half2_rn(o0);
        if (row1 < NN) *(__half2*)(out + (size_t)row1 * 128 + col) = __float22half2_rn(o1);
    }
}

// ---------------- layer-2 finalize + classifier (fused), warp per node ----------------
// ts: [NN][128] fp16; cols 0-63 = t = h1@Wl2 (to aggregate), cols 64-127 = s = h1@Wr2
__global__ void finalize_classifier(const __half* __restrict__ ts, const float* __restrict__ b2,
                                    const float* __restrict__ Wc1, const float* __restrict__ bc1,
                                    const float* __restrict__ Wc2, const float* __restrict__ bc2,
                                    float* __restrict__ out) {
    int gid  = blockIdx.x * blockDim.x + threadIdx.x;
    int node = gid >> 5;
    int lane = gid & 31;
    if (node >= NN) return;

    const int* idx = g_srcidx + g_rowptr[node];
    int n = g_cnt[node];
    float2 acc = make_float2(0.f, 0.f);
    int j = 0;
    for (; j + 4 <= n; j += 4) {
        int s0 = idx[j], s1 = idx[j + 1], s2 = idx[j + 2], s3 = idx[j + 3];
        float2 v0 = __half22float2(*(const __half2*)(ts + (size_t)s0 * 128 + lane * 2));
        float2 v1 = __half22float2(*(const __half2*)(ts + (size_t)s1 * 128 + lane * 2));
        float2 v2 = __half22float2(*(const __half2*)(ts + (size_t)s2 * 128 + lane * 2));
        float2 v3 = __half22float2(*(const __half2*)(ts + (size_t)s3 * 128 + lane * 2));
        acc.x += (v0.x + v1.x) + (v2.x + v3.x);
        acc.y += (v0.y + v1.y) + (v2.y + v3.y);
    }
    for (; j < n; j++) {
        float2 v = __half22float2(*(const __half2*)(ts + (size_t)idx[j] * 128 + lane * 2));
        acc.x += v.x; acc.y += v.y;
    }
    float sc = g_invdeg[node];
    float2 s = __half22float2(*(const __half2*)(ts + (size_t)node * 128 + 64 + lane * 2));
    float vx = acc.x * sc + s.x + __ldg(b2 + lane * 2);
    float vy = acc.y * sc + s.y + __ldg(b2 + lane * 2 + 1);

    float h = __ldg(bc1 + lane);
#pragma unroll
    for (int k = 0; k < 32; k++) {
        float ax = __shfl_sync(0xffffffffu, vx, k);
        float ay = __shfl_sync(0xffffffffu, vy, k);
        h = fmaf(ax, __ldg(Wc1 + (2 * k) * 32 + lane), h);
        h = fmaf(ay, __ldg(Wc1 + (2 * k + 1) * 32 + lane), h);
    }
    h = fmaxf(h, 0.0f);

    float p = h * __ldg(Wc2 + lane);
#pragma unroll
    for (int o = 16; o > 0; o >>= 1) p += __shfl_xor_sync(0xffffffffu, p, o);

    if (lane == 0) out[node] = 1.0f / (1.0f + expf(-(p + bc2[0])));
}

// ---------------- launch ----------------
extern "C" void kernel_launch(void* const* d_in, const int* in_sizes, int n_in,
                              void* d_out, int out_size) {
    const float* x   = (const float*)d_in[0];
    const void*  ei  = d_in[1];
    const float* Wl0 = (const float*)d_in[2];
    const float* Wr0 = (const float*)d_in[3];
    const float* b0  = (const float*)d_in[4];
    const float* Wl1 = (const float*)d_in[5];
    const float* Wr1 = (const float*)d_in[6];
    const float* b1  = (const float*)d_in[7];
    const float* Wl2 = (const float*)d_in[8];
    const float* Wr2 = (const float*)d_in[9];
    const float* b2  = (const float*)d_in[10];
    const float* Wc1 = (const float*)d_in[11];
    const float* bc1 = (const float*)d_in[12];
    const float* Wc2 = (const float*)d_in[13];
    const float* bc2 = (const float*)d_in[14];
    float* out = (float*)d_out;

    __half *aggh, *tsh, *xh, *h0h, *h1h, *wt;
    cudaGetSymbolAddress((void**)&aggh, g_aggh);
    cudaGetSymbolAddress((void**)&tsh, g_tsh);
    cudaGetSymbolAddress((void**)&xh, g_xh);
    cudaGetSymbolAddress((void**)&h0h, g_h0h);
    cudaGetSymbolAddress((void**)&h1h, g_h1h);
    cudaGetSymbolAddress((void**)&wt, g_wt);

    const int SMEM_SZ = 2 * 24576;  // 48KB (double-buffered 24KB stages)
    cudaFuncSetAttribute((void*)gemm_f16<64, true, true, true>,
                         cudaFuncAttributeMaxDynamicSharedMemorySize, SMEM_SZ);
    cudaFuncSetAttribute((void*)gemm_f16<128, true, true, true>,
                         cudaFuncAttributeMaxDynamicSharedMemorySize, SMEM_SZ);
    cudaFuncSetAttribute((void*)gemm_f16<128, false, false, false>,
                         cudaFuncAttributeMaxDynamicSharedMemorySize, SMEM_SZ);

    const int NB_SCAN = (NN + 511) / 512;  // 98

    // CSR build (shared by all 3 layers)
    detect_zero<<<(NN + 255) / 256, 256>>>((const int*)ei);
    count_deg<<<(NE + 255) / 256, 256>>>(ei);
    scan1<<<NB_SCAN, 512>>>();
    scan23<<<(NN + 255) / 256, 256>>>(NB_SCAN);
    fill_csr<<<(NE + 255) / 256, 256>>>(ei);

    // weights -> fp16 transposed + x -> fp16, one kernel
    prep<<<48 + 1024, 256>>>(x, Wl0, Wr0, Wl1, Wr1, Wl2, Wr2);

    const int GEMM_GRID = (NNP + 63) / 64;  // 782

    // layer 0: agg(x_h) fp16 + x_h self -> h0 fp16
    agg_f16<16><<<(NN * 16 + 255) / 256, 256>>>(xh, aggh);
    gemm_f16<64, true, true, true><<<GEMM_GRID, 256, SMEM_SZ>>>(
        aggh, xh, wt + 0 * 16384, wt + 1 * 16384, b0, h0h);

    // layer 1: agg(h0_h) fp16 + h0_h self -> h1 fp16
    agg_f16<32><<<(NN * 32 + 255) / 256, 256>>>(h0h, aggh);
    gemm_f16<128, true, true, true><<<GEMM_GRID, 256, SMEM_SZ>>>(
        aggh, h0h, wt + 2 * 16384, wt + 3 * 16384, b1, h1h);

    // layer 2: transform-first. ts = h1 @ [Wl2 | Wr2] fp16 (cols 0-63 = t, 64-127 = s)
    gemm_f16<128, false, false, false><<<GEMM_GRID, 256, SMEM_SZ>>>(
        h1h, h1h, wt + 4 * 16384, wt + 4 * 16384, (const float*)0, tsh);

    // finalize layer 2 (64-wide fp16 gather) + classifier, fused
    finalize_classifier<<<(NN * 32 + 255) / 256, 256>>>(tsh, b2, Wc1, bc1, Wc2, bc2, out);
}